// round 3
// baseline (speedup 1.0000x reference)
#include <cuda_runtime.h>
#include <math.h>

#define MTOT 16384   // B*S
#define G3   2304    // 3*H
#define HID  768
#define NC   9
#define NBLK 128     // persistent GRU blocks

// ---------------- device scratch ----------------
__device__ float g_qkv[(size_t)MTOT * G3];
__device__ float g_scores[(size_t)256 * 512 * 512];
__device__ float g_att[(size_t)MTOT * 768];
__device__ float g_x[(size_t)MTOT * 768];
__device__ float g_xw[(size_t)2 * MTOT * G3];          // [dir][(b*512+s)][G3]
__device__ float g_xwT[(size_t)2 * 512 * G3 * 32];     // [dir][s][g][b]
__device__ float g_hseqT[(size_t)512 * 1536 * 32];     // [s][dir*768+u][b]
__device__ float g_h0[(size_t)MTOT * 1536];
__device__ float g_h1[(size_t)MTOT * 1536];
__device__ float g_hping[2 * 2 * HID * 32];            // [parity][dir][u][b]
__device__ int   g_flags[NBLK];
__device__ float g_em[(size_t)MTOT * NC];
__device__ float g_nll[32];

// ---------------- C[M,N] = A[M,K] @ B[N,K]^T + bias ; M%128==0, N%128==0, K%8==0
__global__ void __launch_bounds__(256) sgemm128(
    const float* __restrict__ A, const float* __restrict__ B,
    const float* __restrict__ bias, float* __restrict__ C,
    int M, int N, int K)
{
    __shared__ float As[8][132];
    __shared__ float Bs[8][132];
    const int t = threadIdx.x;
    const int row0 = blockIdx.y * 128;
    const int col0 = blockIdx.x * 128;
    const int lr = t >> 1;
    const int lk = (t & 1) * 4;
    const int tx = t & 15, ty = t >> 4;

    const float* Ap = A + (size_t)(row0 + lr) * K + lk;
    const float* Bp = B + (size_t)(col0 + lr) * K + lk;

    float acc[8][8];
#pragma unroll
    for (int i = 0; i < 8; i++)
#pragma unroll
        for (int j = 0; j < 8; j++) acc[i][j] = 0.f;

    for (int k0 = 0; k0 < K; k0 += 8) {
        float4 av = *(const float4*)(Ap + k0);
        float4 bv = *(const float4*)(Bp + k0);
        __syncthreads();
        As[lk + 0][lr] = av.x; As[lk + 1][lr] = av.y; As[lk + 2][lr] = av.z; As[lk + 3][lr] = av.w;
        Bs[lk + 0][lr] = bv.x; Bs[lk + 1][lr] = bv.y; Bs[lk + 2][lr] = bv.z; Bs[lk + 3][lr] = bv.w;
        __syncthreads();
#pragma unroll
        for (int kk = 0; kk < 8; kk++) {
            float a[8], b[8];
            *(float4*)(a)     = *(const float4*)&As[kk][ty * 8];
            *(float4*)(a + 4) = *(const float4*)&As[kk][ty * 8 + 4];
            *(float4*)(b)     = *(const float4*)&Bs[kk][tx * 8];
            *(float4*)(b + 4) = *(const float4*)&Bs[kk][tx * 8 + 4];
#pragma unroll
            for (int i = 0; i < 8; i++)
#pragma unroll
                for (int j = 0; j < 8; j++)
                    acc[i][j] = fmaf(a[i], b[j], acc[i][j]);
        }
    }
    float bb[8];
#pragma unroll
    for (int j = 0; j < 8; j++) bb[j] = bias[col0 + tx * 8 + j];
#pragma unroll
    for (int i = 0; i < 8; i++) {
        float* Cp = C + (size_t)(row0 + ty * 8 + i) * N + col0 + tx * 8;
        float4 v0 = make_float4(acc[i][0] + bb[0], acc[i][1] + bb[1], acc[i][2] + bb[2], acc[i][3] + bb[3]);
        float4 v1 = make_float4(acc[i][4] + bb[4], acc[i][5] + bb[5], acc[i][6] + bb[6], acc[i][7] + bb[7]);
        *(float4*)(Cp) = v0;
        *(float4*)(Cp + 4) = v1;
    }
}

// ---------------- attention scores = scale * Q K^T ----------------
__global__ void __launch_bounds__(256) attn_scores(void)
{
    __shared__ float Qs[16][64];
    __shared__ float Ks[16][64];
    const int bh = blockIdx.z, b = bh >> 3, h = bh & 7;
    const int row0 = blockIdx.y * 64, col0 = blockIdx.x * 64;
    const int t = threadIdx.x;
    const int lr = t & 63, lk = (t >> 6) << 2;
    const int tx = t & 15, ty = t >> 4;

    const float* Qp = g_qkv + ((size_t)b * 512 + row0 + lr) * G3 + h * 96 + lk;
    const float* Kp = g_qkv + ((size_t)b * 512 + col0 + lr) * G3 + 768 + h * 96 + lk;

    float acc[4][4];
#pragma unroll
    for (int i = 0; i < 4; i++)
#pragma unroll
        for (int j = 0; j < 4; j++) acc[i][j] = 0.f;

    for (int k0 = 0; k0 < 96; k0 += 16) {
        float4 qv = *(const float4*)(Qp + k0);
        float4 kv = *(const float4*)(Kp + k0);
        __syncthreads();
        Qs[lk + 0][lr] = qv.x; Qs[lk + 1][lr] = qv.y; Qs[lk + 2][lr] = qv.z; Qs[lk + 3][lr] = qv.w;
        Ks[lk + 0][lr] = kv.x; Ks[lk + 1][lr] = kv.y; Ks[lk + 2][lr] = kv.z; Ks[lk + 3][lr] = kv.w;
        __syncthreads();
#pragma unroll
        for (int kk = 0; kk < 16; kk++) {
            float a[4], c[4];
            *(float4*)a = *(const float4*)&Qs[kk][ty << 2];
            *(float4*)c = *(const float4*)&Ks[kk][tx << 2];
#pragma unroll
            for (int i = 0; i < 4; i++)
#pragma unroll
                for (int j = 0; j < 4; j++)
                    acc[i][j] = fmaf(a[i], c[j], acc[i][j]);
        }
    }
    const float scale = 0.1020620726159657f; // 1/sqrt(96)
    float* Cb = g_scores + (size_t)bh * 262144;
#pragma unroll
    for (int i = 0; i < 4; i++)
#pragma unroll
        for (int j = 0; j < 4; j++)
            Cb[(size_t)(row0 + (ty << 2) + i) * 512 + col0 + (tx << 2) + j] = acc[i][j] * scale;
}

// ---------------- softmax over rows of 512 (warp per row) ----------------
__global__ void __launch_bounds__(256) attn_softmax(void)
{
    const int warp = threadIdx.x >> 5, lane = threadIdx.x & 31;
    const size_t row = (size_t)blockIdx.x * 8 + warp;
    float* p = g_scores + row * 512;
    float v[16];
    float m = -1e30f;
#pragma unroll
    for (int i = 0; i < 16; i++) { v[i] = p[lane + (i << 5)]; m = fmaxf(m, v[i]); }
#pragma unroll
    for (int o = 16; o; o >>= 1) m = fmaxf(m, __shfl_xor_sync(0xffffffffu, m, o));
    float s = 0.f;
#pragma unroll
    for (int i = 0; i < 16; i++) { v[i] = expf(v[i] - m); s += v[i]; }
#pragma unroll
    for (int o = 16; o; o >>= 1) s += __shfl_xor_sync(0xffffffffu, s, o);
    const float inv = 1.f / s;
#pragma unroll
    for (int i = 0; i < 16; i++) p[lane + (i << 5)] = v[i] * inv;
}

// ---------------- O = P V ----------------
__global__ void __launch_bounds__(256) attn_av(void)
{
    __shared__ float Ps[32][64];
    __shared__ float Vs[32][96];
    const int bh = blockIdx.y, b = bh >> 3, h = bh & 7;
    const int row0 = blockIdx.x * 64;
    const int t = threadIdx.x;
    const int tx = t & 15, ty = t >> 4;
    const int lr = t & 63, lk = (t >> 6) << 3;
    const int kr = t >> 3, cq = (t & 7) * 12;

    const float* Pp = g_scores + (size_t)bh * 262144 + (size_t)(row0 + lr) * 512 + lk;
    const float* Vp = g_qkv + ((size_t)b * 512 + kr) * G3 + 1536 + h * 96 + cq;

    float acc[4][6];
#pragma unroll
    for (int i = 0; i < 4; i++)
#pragma unroll
        for (int j = 0; j < 6; j++) acc[i][j] = 0.f;

    for (int k0 = 0; k0 < 512; k0 += 32) {
        float4 p0 = *(const float4*)(Pp + k0);
        float4 p1 = *(const float4*)(Pp + k0 + 4);
        const float* vp = Vp + (size_t)k0 * G3;
        float4 v0 = *(const float4*)(vp);
        float4 v1 = *(const float4*)(vp + 4);
        float4 v2 = *(const float4*)(vp + 8);
        __syncthreads();
        Ps[lk + 0][lr] = p0.x; Ps[lk + 1][lr] = p0.y; Ps[lk + 2][lr] = p0.z; Ps[lk + 3][lr] = p0.w;
        Ps[lk + 4][lr] = p1.x; Ps[lk + 5][lr] = p1.y; Ps[lk + 6][lr] = p1.z; Ps[lk + 7][lr] = p1.w;
        *(float4*)&Vs[kr][cq + 0] = v0;
        *(float4*)&Vs[kr][cq + 4] = v1;
        *(float4*)&Vs[kr][cq + 8] = v2;
        __syncthreads();
#pragma unroll
        for (int kk = 0; kk < 32; kk++) {
            float a[4];
            *(float4*)a = *(const float4*)&Ps[kk][ty << 2];
            const float* vr = &Vs[kk][tx * 6];
#pragma unroll
            for (int i = 0; i < 4; i++)
#pragma unroll
                for (int j = 0; j < 6; j++)
                    acc[i][j] = fmaf(a[i], vr[j], acc[i][j]);
        }
    }
#pragma unroll
    for (int i = 0; i < 4; i++) {
        size_t r = (size_t)b * 512 + row0 + (ty << 2) + i;
#pragma unroll
        for (int j = 0; j < 6; j++)
            g_att[r * 768 + h * 96 + tx * 6 + j] = acc[i][j];
    }
}

// ---------------- T1: xw [dir][(b*512+s)][G3] -> xwT [dir][s][g][b] ----------------
__global__ void __launch_bounds__(256) xw_transpose(void)
{
    __shared__ float tile[32][65];
    const int g0 = blockIdx.x * 64, s = blockIdx.y, dir = blockIdx.z;
    const int t = threadIdx.x;
    const float* in = g_xw + (size_t)dir * MTOT * G3;
    {
        const int b = t >> 3, q = t & 7;
        const float* src = in + ((size_t)(b * 512 + s)) * G3 + g0 + q * 8;
        float4 v0 = *(const float4*)(src);
        float4 v1 = *(const float4*)(src + 4);
        tile[b][q * 8 + 0] = v0.x; tile[b][q * 8 + 1] = v0.y;
        tile[b][q * 8 + 2] = v0.z; tile[b][q * 8 + 3] = v0.w;
        tile[b][q * 8 + 4] = v1.x; tile[b][q * 8 + 5] = v1.y;
        tile[b][q * 8 + 6] = v1.z; tile[b][q * 8 + 7] = v1.w;
    }
    __syncthreads();
    {
        const int g = t >> 2, bq = (t & 3) * 8;
        float o[8];
#pragma unroll
        for (int j = 0; j < 8; j++) o[j] = tile[bq + j][g];
        float* dst = g_xwT + ((size_t)(dir * 512 + s) * G3 + g0 + g) * 32 + bq;
        *(float4*)(dst)     = make_float4(o[0], o[1], o[2], o[3]);
        *(float4*)(dst + 4) = make_float4(o[4], o[5], o[6], o[7]);
    }
}

// ---------------- T2: hseqT [s][c][b] -> hseq [(b*512+s)][1536] ----------------
__global__ void __launch_bounds__(256) hseq_transpose(float* __restrict__ out)
{
    __shared__ float tile[64][33];
    const int c0 = blockIdx.x * 64, s = blockIdx.y;
    const int t = threadIdx.x;
    {
        const int c = t >> 2, bq = (t & 3) * 8;
        const float* src = g_hseqT + ((size_t)s * 1536 + c0 + c) * 32 + bq;
        float4 v0 = *(const float4*)(src);
        float4 v1 = *(const float4*)(src + 4);
        tile[c][bq + 0] = v0.x; tile[c][bq + 1] = v0.y; tile[c][bq + 2] = v0.z; tile[c][bq + 3] = v0.w;
        tile[c][bq + 4] = v1.x; tile[c][bq + 5] = v1.y; tile[c][bq + 6] = v1.z; tile[c][bq + 7] = v1.w;
    }
    __syncthreads();
    {
        const int b = t >> 3, q = t & 7;
        float o[8];
#pragma unroll
        for (int j = 0; j < 8; j++) o[j] = tile[q * 8 + j][b];
        float* dst = out + ((size_t)(b * 512 + s)) * 1536 + c0 + q * 8;
        *(float4*)(dst)     = make_float4(o[0], o[1], o[2], o[3]);
        *(float4*)(dst + 4) = make_float4(o[4], o[5], o[6], o[7]);
    }
}

// ---------------- reset flags + h ping-pong ----------------
__global__ void gru_reset(void)
{
    int i = blockIdx.x * 256 + threadIdx.x;   // grid 384 x 256 = 98304
    if (i < NBLK) g_flags[i] = 0;
    g_hping[i] = 0.f;
}

// ---------------- persistent GRU layer ----------------
// grid (64, 2dirs), 288 threads, dynamic smem.
// block: 12 units (36 gate-rows) x 32 batches, all 512 steps, 1 grid barrier/step.
__global__ void __launch_bounds__(288) gru_layer(
    const float* __restrict__ whhF, const float* __restrict__ whhB,
    const float* __restrict__ bhhF, const float* __restrict__ bhhB)
{
    extern __shared__ float sm[];
    float* hs  = sm;                  // 768*32 = 24576
    float* ws  = sm + 24576;          // 2 * 36 * 100 = 7200
    float* ghs = sm + 24576 + 7200;   // 36*32 = 1152
    float* bsh = ghs + 1152;          // 36

    const int tid = threadIdx.x;
    const int ub  = blockIdx.x;           // 0..63
    const int dir = blockIdx.y;
    const int blk = dir * 64 + ub;
    const int u0  = ub * 12;
    const float* W   = dir ? whhB : whhF;
    const float* bhh = dir ? bhhB : bhhF;
    const float* xwT = g_xwT + (size_t)dir * 512 * G3 * 32;

    const int r  = tid >> 3;    // row 0..35
    const int bg = tid & 7;     // batch quad

    if (tid < 36) {
        int gate = tid / 12, uu = u0 + tid % 12;
        bsh[tid] = bhh[gate * 768 + uu];
    }

    for (int s = 0; s < 512; s++) {
        // ---- grid barrier: wait for all blocks to finish step s-1 ----
        if (s > 0) {
            if (tid < 32) {
                for (;;) {
                    int bad = 0;
#pragma unroll
                    for (int q = 0; q < 4; q++)
                        bad |= (((volatile int*)g_flags)[tid * 4 + q] < s);
                    if (!__any_sync(0xffffffffu, bad)) break;
                    __nanosleep(64);
                }
            }
        }
        __syncthreads();

        const int rp = s & 1;
        const float* hsrc = g_hping + (size_t)((rp * 2 + dir) * HID) * 32;
        // load h into smem
        for (int f = tid; f < 6144; f += 288)
            ((float4*)hs)[f] = ((const float4*)hsrc)[f];

        // prologue: load W chunk 0
        float4 pv[3];
#pragma unroll
        for (int tt = 0; tt < 3; tt++) {
            int f = tid + tt * 288;
            int i = f / 24, kk = (f % 24) * 4;
            int gr = (i / 12) * 768 + u0 + (i % 12);
            pv[tt] = *(const float4*)&W[(size_t)gr * 768 + kk];
        }
#pragma unroll
        for (int tt = 0; tt < 3; tt++) {
            int f = tid + tt * 288;
            int i = f / 24, kk = (f % 24) * 4;
            *(float4*)&ws[i * 100 + kk] = pv[tt];
        }

        float4 acc = make_float4(0.f, 0.f, 0.f, 0.f);
        for (int c = 0; c < 8; c++) {
            if (c < 7) {
                int kb = (c + 1) * 96;
#pragma unroll
                for (int tt = 0; tt < 3; tt++) {
                    int f = tid + tt * 288;
                    int i = f / 24, kk = (f % 24) * 4;
                    int gr = (i / 12) * 768 + u0 + (i % 12);
                    pv[tt] = *(const float4*)&W[(size_t)gr * 768 + kb + kk];
                }
            }
            __syncthreads();   // ws[c&1] ready, hs ready (c==0)
            const float* wrow = &ws[(c & 1) * 3600 + r * 100];
            const int kbase = c * 96;
#pragma unroll 4
            for (int kk = 0; kk < 96; kk += 4) {
                float4 w4 = *(const float4*)&wrow[kk];
                const float* hp = &hs[(kbase + kk) * 32 + bg * 4];
                float4 h0 = *(const float4*)(hp);
                float4 h1 = *(const float4*)(hp + 32);
                float4 h2 = *(const float4*)(hp + 64);
                float4 h3 = *(const float4*)(hp + 96);
                acc.x = fmaf(w4.x, h0.x, acc.x); acc.y = fmaf(w4.x, h0.y, acc.y);
                acc.z = fmaf(w4.x, h0.z, acc.z); acc.w = fmaf(w4.x, h0.w, acc.w);
                acc.x = fmaf(w4.y, h1.x, acc.x); acc.y = fmaf(w4.y, h1.y, acc.y);
                acc.z = fmaf(w4.y, h1.z, acc.z); acc.w = fmaf(w4.y, h1.w, acc.w);
                acc.x = fmaf(w4.z, h2.x, acc.x); acc.y = fmaf(w4.z, h2.y, acc.y);
                acc.z = fmaf(w4.z, h2.z, acc.z); acc.w = fmaf(w4.z, h2.w, acc.w);
                acc.x = fmaf(w4.w, h3.x, acc.x); acc.y = fmaf(w4.w, h3.y, acc.y);
                acc.z = fmaf(w4.w, h3.z, acc.z); acc.w = fmaf(w4.w, h3.w, acc.w);
            }
            if (c < 7) {
                __syncthreads();   // everyone done with ws[(c+1)&1] from 2 chunks ago
#pragma unroll
                for (int tt = 0; tt < 3; tt++) {
                    int f = tid + tt * 288;
                    int i = f / 24, kk = (f % 24) * 4;
                    *(float4*)&ws[((c + 1) & 1) * 3600 + i * 100 + kk] = pv[tt];
                }
            }
        }
        *(float4*)&ghs[r * 32 + bg * 4] = acc;
        __syncthreads();

        // ---- gates ----
        const int sx = dir ? (511 - s) : s;
        const int wp = (s & 1) ^ 1;
        float* hdst = g_hping + (size_t)((wp * 2 + dir) * HID) * 32;
        const float* xwrow = xwT + (size_t)sx * G3 * 32;
        for (int p = tid; p < 384; p += 288) {
            int j = p >> 5, b = p & 31;
            int ug = u0 + j;
            float xr = xwrow[(size_t)(ug) * 32 + b];
            float xz = xwrow[(size_t)(768 + ug) * 32 + b];
            float xn = xwrow[(size_t)(1536 + ug) * 32 + b];
            float hr = ghs[j * 32 + b]        + bsh[j];
            float hz = ghs[(12 + j) * 32 + b] + bsh[12 + j];
            float hn = ghs[(24 + j) * 32 + b] + bsh[24 + j];
            float rr = 1.f / (1.f + expf(-(xr + hr)));
            float zz = 1.f / (1.f + expf(-(xz + hz)));
            float nn = tanhf(xn + rr * hn);
            float hold = hs[ug * 32 + b];
            float hnew = (1.f - zz) * nn + zz * hold;
            hdst[ug * 32 + b] = hnew;
            g_hseqT[((size_t)sx * 1536 + dir * 768 + ug) * 32 + b] = hnew;
        }

        __threadfence();
        __syncthreads();
        if (tid == 0) ((volatile int*)g_flags)[blk] = s + 1;
    }
}

// ---------------- FC: em = h1 @ fc_w^T + fc_b (warp per row) ----------------
__global__ void __launch_bounds__(256) fc_kernel(
    const float* __restrict__ h1, const float* __restrict__ fcw,
    const float* __restrict__ fcb)
{
    int warp = threadIdx.x >> 5, lane = threadIdx.x & 31;
    int row = blockIdx.x * 8 + warp;
    const float* hp = h1 + (size_t)row * 1536;
    for (int c = 0; c < NC; c++) {
        const float* wp = fcw + c * 1536;
        float s = 0.f;
        for (int k = lane; k < 1536; k += 32) s = fmaf(hp[k], wp[k], s);
#pragma unroll
        for (int o = 16; o; o >>= 1) s += __shfl_xor_sync(0xffffffffu, s, o);
        if (lane == 0) g_em[(size_t)row * NC + c] = s + fcb[c];
    }
}

// ---------------- CRF NLL (one warp per batch) ----------------
__global__ void crf_nll_kernel(
    const int* __restrict__ labels, const float* __restrict__ start,
    const float* __restrict__ endw, const float* __restrict__ trans)
{
    int b = blockIdx.x;
    int j = threadIdx.x;
    __shared__ float al[2][NC];
    __shared__ float tr[NC * NC];
    for (int i = j; i < NC * NC; i += 32) tr[i] = trans[i];
    const float* e = g_em + (size_t)b * 512 * NC;
    if (j < NC) al[0][j] = start[j] + e[j];
    __syncwarp();
    for (int t = 1; t < 512; t++) {
        int cur = t & 1, prv = cur ^ 1;
        if (j < NC) {
            float m = -1e30f;
#pragma unroll
            for (int i = 0; i < NC; i++) m = fmaxf(m, al[prv][i] + tr[i * NC + j]);
            float s = 0.f;
#pragma unroll
            for (int i = 0; i < NC; i++) s += expf(al[prv][i] + tr[i * NC + j] - m);
            al[cur][j] = m + logf(s) + e[t * NC + j];
        }
        __syncwarp();
    }
    const int* lab = labels + b * 512;
    float acc = 0.f;
    for (int t = j; t < 512; t += 32) acc += e[t * NC + lab[t]];
    for (int t = j; t < 511; t += 32) acc += tr[lab[t] * NC + lab[t + 1]];
#pragma unroll
    for (int o = 16; o; o >>= 1) acc += __shfl_xor_sync(0xffffffffu, acc, o);
    if (j == 0) {
        float m = -1e30f;
#pragma unroll
        for (int jj = 0; jj < NC; jj++) m = fmaxf(m, al[1][jj] + endw[jj]);
        float s = 0.f;
#pragma unroll
        for (int jj = 0; jj < NC; jj++) s += expf(al[1][jj] + endw[jj] - m);
        float denom = m + logf(s);
        float num = acc + start[lab[0]] + endw[lab[511]];
        g_nll[b] = denom - num;
    }
}

__global__ void finalize_loss(float* out)
{
    float s = 0.f;
    for (int i = 0; i < 32; i++) s += g_nll[i];
    out[0] = s;
}

// ---------------- Viterbi (one warp per batch) ----------------
__global__ void viterbi_kernel(
    const float* __restrict__ start, const float* __restrict__ endw,
    const float* __restrict__ trans, float* __restrict__ out)
{
    int b = blockIdx.x;
    int j = threadIdx.x;
    __shared__ float al[2][NC];
    __shared__ float tr[NC * NC];
    __shared__ unsigned char bp[511][NC];
    for (int i = j; i < NC * NC; i += 32) tr[i] = trans[i];
    const float* e = g_em + (size_t)b * 512 * NC;
    if (j < NC) al[0][j] = start[j] + e[j];
    __syncwarp();
    for (int t = 1; t < 512; t++) {
        int cur = t & 1, prv = cur ^ 1;
        if (j < NC) {
            float best = -1e30f;
            int arg = 0;
#pragma unroll
            for (int i = 0; i < NC; i++) {
                float sc = al[prv][i] + tr[i * NC + j];
                if (sc > best) { best = sc; arg = i; }
            }
            al[cur][j] = best + e[t * NC + j];
            bp[t - 1][j] = (unsigned char)arg;
        }
        __syncwarp();
    }
    if (j == 0) {
        float best = -1e30f;
        int last = 0;
#pragma unroll
        for (int jj = 0; jj < NC; jj++) {
            float sc = al[1][jj] + endw[jj];
            if (sc > best) { best = sc; last = jj; }
        }
        float* po = out + 1 + (size_t)b * 512;
        po[511] = (float)last;
        int tag = last;
        for (int t = 510; t >= 0; t--) {
            tag = bp[t][tag];
            po[t] = (float)tag;
        }
    }
}

// ---------------- launch ----------------
extern "C" void kernel_launch(void* const* d_in, const int* in_sizes, int n_in,
                              void* d_out, int out_size)
{
    const float* emb   = (const float*)d_in[0];
    const float* ipw   = (const float*)d_in[1];
    const float* ipb   = (const float*)d_in[2];
    const float* opw   = (const float*)d_in[3];
    const float* opb   = (const float*)d_in[4];
    const float* fcw   = (const float*)d_in[5];
    const float* fcb   = (const float*)d_in[6];
    const float* cstart= (const float*)d_in[7];
    const float* cend  = (const float*)d_in[8];
    const float* ctr   = (const float*)d_in[9];
    const int*   lab   = (const int*)d_in[10];
    const float* wih0f = (const float*)d_in[11];
    const float* whh0f = (const float*)d_in[12];
    const float* bih0f = (const float*)d_in[13];
    const float* bhh0f = (const float*)d_in[14];
    const float* wih0b = (const float*)d_in[15];
    const float* whh0b = (const float*)d_in[16];
    const float* bih0b = (const float*)d_in[17];
    const float* bhh0b = (const float*)d_in[18];
    const float* wih1f = (const float*)d_in[19];
    const float* whh1f = (const float*)d_in[20];
    const float* bih1f = (const float*)d_in[21];
    const float* bhh1f = (const float*)d_in[22];
    const float* wih1b = (const float*)d_in[23];
    const float* whh1b = (const float*)d_in[24];
    const float* bih1b = (const float*)d_in[25];
    const float* bhh1b = (const float*)d_in[26];
    float* out = (float*)d_out;

    static int smem_set = 0;
    const int GRU_SMEM = (24576 + 7200 + 1152 + 64) * 4;
    if (!smem_set) {
        cudaFuncSetAttribute(gru_layer, cudaFuncAttributeMaxDynamicSharedMemorySize, GRU_SMEM);
        smem_set = 1;
    }

    void* p;
    cudaGetSymbolAddress(&p, g_qkv);  float* qkv = (float*)p;
    cudaGetSymbolAddress(&p, g_att);  float* att = (float*)p;
    cudaGetSymbolAddress(&p, g_x);    float* x   = (float*)p;
    cudaGetSymbolAddress(&p, g_xw);   float* xw  = (float*)p;
    cudaGetSymbolAddress(&p, g_h0);   float* h0  = (float*)p;
    cudaGetSymbolAddress(&p, g_h1);   float* h1  = (float*)p;

    // 1. QKV projection
    sgemm128<<<dim3(G3 / 128, MTOT / 128), 256>>>(emb, ipw, ipb, qkv, MTOT, G3, 768);
    // 2. attention
    attn_scores<<<dim3(8, 8, 256), 256>>>();
    attn_softmax<<<16384, 256>>>();
    attn_av<<<dim3(8, 256), 256>>>();
    // 3. out projection
    sgemm128<<<dim3(768 / 128, MTOT / 128), 256>>>(att, opw, opb, x, MTOT, 768, 768);

    // 4. GRU layers
    for (int l = 0; l < 2; l++) {
        const float* xin  = l ? h0 : x;
        int K             = l ? 1536 : 768;
        const float* wihF = l ? wih1f : wih0f;
        const float* wihB = l ? wih1b : wih0b;
        const float* bihF = l ? bih1f : bih0f;
        const float* bihB = l ? bih1b : bih0b;
        const float* whhF = l ? whh1f : whh0f;
        const float* whhB = l ? whh1b : whh0b;
        const float* bhhF = l ? bhh1f : bhh0f;
        const float* bhhB = l ? bhh1b : bhh0b;
        float* hseq       = l ? h1 : h0;

        sgemm128<<<dim3(G3 / 128, MTOT / 128), 256>>>(xin, wihF, bihF, xw, MTOT, G3, K);
        sgemm128<<<dim3(G3 / 128, MTOT / 128), 256>>>(xin, wihB, bihB, xw + (size_t)MTOT * G3, MTOT, G3, K);
        xw_transpose<<<dim3(36, 512, 2), 256>>>();
        gru_reset<<<384, 256>>>();
        gru_layer<<<dim3(64, 2), 288, GRU_SMEM>>>(whhF, whhB, bhhF, bhhB);
        hseq_transpose<<<dim3(24, 512), 256>>>(hseq);
    }

    // 5. FC + CRF + Viterbi
    fc_kernel<<<MTOT / 8, 256>>>(h1, fcw, fcb);
    crf_nll_kernel<<<32, 32>>>(lab, cstart, cend, ctr);
    finalize_loss<<<1, 1>>>(out);
    viterbi_kernel<<<32, 32>>>(cstart, cend, ctr, out);
}

// round 5
// speedup vs baseline: 1.1575x; 1.1575x over previous
#include <cuda_runtime.h>
#include <math.h>

#define MTOT 16384   // B*S
#define G3   2304    // 3*H
#define HID  768
#define NC   9
#define NBLK 128     // persistent GRU blocks

// ---------------- device scratch ----------------
__device__ float g_qkv[(size_t)MTOT * G3];
__device__ float g_scores[(size_t)256 * 512 * 512];
__device__ float g_att[(size_t)MTOT * 768];
__device__ float g_x[(size_t)MTOT * 768];
__device__ float g_xw[(size_t)2 * MTOT * G3];          // [dir][(b*512+s)][G3]
__device__ float g_xwT[(size_t)2 * 512 * G3 * 32];     // [dir][s][g][b]
__device__ float g_hseqT[(size_t)512 * 1536 * 32];     // [s][dir*768+u][b]
__device__ float g_h0[(size_t)MTOT * 1536];
__device__ float g_h1[(size_t)MTOT * 1536];
__device__ float g_hping[2 * 2 * HID * 32];            // [parity][dir][u][b]
__device__ int   g_flags[NBLK];
__device__ float g_em[(size_t)MTOT * NC];
__device__ float g_nll[32];

// ---------------- packed fp32x2 helpers (sm_100+) ----------------
__device__ __forceinline__ unsigned long long f2pack(float lo, float hi) {
    unsigned long long r;
    asm("mov.b64 %0, {%1, %2};" : "=l"(r) : "f"(lo), "f"(hi));
    return r;
}
__device__ __forceinline__ void f2unpack(unsigned long long v, float& lo, float& hi) {
    asm("mov.b64 {%0, %1}, %2;" : "=f"(lo), "=f"(hi) : "l"(v));
}
__device__ __forceinline__ unsigned long long f2fma(unsigned long long a, unsigned long long b, unsigned long long c) {
    unsigned long long d;
    asm("fma.rn.f32x2 %0, %1, %2, %3;" : "=l"(d) : "l"(a), "l"(b), "l"(c));
    return d;
}

// ---------------- C[M,N] = A[M,K] @ B[N,K]^T + bias ; M%128==0, N%128==0, K%8==0
__global__ void __launch_bounds__(256) sgemm128(
    const float* __restrict__ A, const float* __restrict__ B,
    const float* __restrict__ bias, float* __restrict__ C,
    int M, int N, int K)
{
    __shared__ float As[8][132];
    __shared__ float Bs[8][132];
    const int t = threadIdx.x;
    const int row0 = blockIdx.y * 128;
    const int col0 = blockIdx.x * 128;
    const int lr = t >> 1;
    const int lk = (t & 1) * 4;
    const int tx = t & 15, ty = t >> 4;

    const float* Ap = A + (size_t)(row0 + lr) * K + lk;
    const float* Bp = B + (size_t)(col0 + lr) * K + lk;

    unsigned long long acc2[8][4];
#pragma unroll
    for (int i = 0; i < 8; i++)
#pragma unroll
        for (int j = 0; j < 4; j++) acc2[i][j] = 0ull;

    for (int k0 = 0; k0 < K; k0 += 8) {
        float4 av = *(const float4*)(Ap + k0);
        float4 bv = *(const float4*)(Bp + k0);
        __syncthreads();
        As[lk + 0][lr] = av.x; As[lk + 1][lr] = av.y; As[lk + 2][lr] = av.z; As[lk + 3][lr] = av.w;
        Bs[lk + 0][lr] = bv.x; Bs[lk + 1][lr] = bv.y; Bs[lk + 2][lr] = bv.z; Bs[lk + 3][lr] = bv.w;
        __syncthreads();
#pragma unroll
        for (int kk = 0; kk < 8; kk++) {
            float a[8];
            *(float4*)(a)     = *(const float4*)&As[kk][ty * 8];
            *(float4*)(a + 4) = *(const float4*)&As[kk][ty * 8 + 4];
            ulonglong2 b01 = *(const ulonglong2*)&Bs[kk][tx * 8];
            ulonglong2 b23 = *(const ulonglong2*)&Bs[kk][tx * 8 + 4];
#pragma unroll
            for (int i = 0; i < 8; i++) {
                unsigned long long ai = f2pack(a[i], a[i]);
                acc2[i][0] = f2fma(ai, b01.x, acc2[i][0]);
                acc2[i][1] = f2fma(ai, b01.y, acc2[i][1]);
                acc2[i][2] = f2fma(ai, b23.x, acc2[i][2]);
                acc2[i][3] = f2fma(ai, b23.y, acc2[i][3]);
            }
        }
    }
    float bb[8];
#pragma unroll
    for (int j = 0; j < 8; j++) bb[j] = bias[col0 + tx * 8 + j];
#pragma unroll
    for (int i = 0; i < 8; i++) {
        float c[8];
#pragma unroll
        for (int j = 0; j < 4; j++) f2unpack(acc2[i][j], c[2 * j], c[2 * j + 1]);
        float* Cp = C + (size_t)(row0 + ty * 8 + i) * N + col0 + tx * 8;
        *(float4*)(Cp)     = make_float4(c[0] + bb[0], c[1] + bb[1], c[2] + bb[2], c[3] + bb[3]);
        *(float4*)(Cp + 4) = make_float4(c[4] + bb[4], c[5] + bb[5], c[6] + bb[6], c[7] + bb[7]);
    }
}

// ---------------- attention scores = scale * Q K^T ----------------
__global__ void __launch_bounds__(256) attn_scores(void)
{
    __shared__ float Qs[16][64];
    __shared__ float Ks[16][64];
    const int bh = blockIdx.z, b = bh >> 3, h = bh & 7;
    const int row0 = blockIdx.y * 64, col0 = blockIdx.x * 64;
    const int t = threadIdx.x;
    const int lr = t & 63, lk = (t >> 6) << 2;
    const int tx = t & 15, ty = t >> 4;

    const float* Qp = g_qkv + ((size_t)b * 512 + row0 + lr) * G3 + h * 96 + lk;
    const float* Kp = g_qkv + ((size_t)b * 512 + col0 + lr) * G3 + 768 + h * 96 + lk;

    float acc[4][4];
#pragma unroll
    for (int i = 0; i < 4; i++)
#pragma unroll
        for (int j = 0; j < 4; j++) acc[i][j] = 0.f;

    for (int k0 = 0; k0 < 96; k0 += 16) {
        float4 qv = *(const float4*)(Qp + k0);
        float4 kv = *(const float4*)(Kp + k0);
        __syncthreads();
        Qs[lk + 0][lr] = qv.x; Qs[lk + 1][lr] = qv.y; Qs[lk + 2][lr] = qv.z; Qs[lk + 3][lr] = qv.w;
        Ks[lk + 0][lr] = kv.x; Ks[lk + 1][lr] = kv.y; Ks[lk + 2][lr] = kv.z; Ks[lk + 3][lr] = kv.w;
        __syncthreads();
#pragma unroll
        for (int kk = 0; kk < 16; kk++) {
            float a[4], c[4];
            *(float4*)a = *(const float4*)&Qs[kk][ty << 2];
            *(float4*)c = *(const float4*)&Ks[kk][tx << 2];
#pragma unroll
            for (int i = 0; i < 4; i++)
#pragma unroll
                for (int j = 0; j < 4; j++)
                    acc[i][j] = fmaf(a[i], c[j], acc[i][j]);
        }
    }
    const float scale = 0.1020620726159657f; // 1/sqrt(96)
    float* Cb = g_scores + (size_t)bh * 262144;
#pragma unroll
    for (int i = 0; i < 4; i++)
#pragma unroll
        for (int j = 0; j < 4; j++)
            Cb[(size_t)(row0 + (ty << 2) + i) * 512 + col0 + (tx << 2) + j] = acc[i][j] * scale;
}

// ---------------- softmax over rows of 512 (warp per row) ----------------
__global__ void __launch_bounds__(256) attn_softmax(void)
{
    const int warp = threadIdx.x >> 5, lane = threadIdx.x & 31;
    const size_t row = (size_t)blockIdx.x * 8 + warp;
    float* p = g_scores + row * 512;
    float v[16];
    float m = -1e30f;
#pragma unroll
    for (int i = 0; i < 16; i++) { v[i] = p[lane + (i << 5)]; m = fmaxf(m, v[i]); }
#pragma unroll
    for (int o = 16; o; o >>= 1) m = fmaxf(m, __shfl_xor_sync(0xffffffffu, m, o));
    float s = 0.f;
#pragma unroll
    for (int i = 0; i < 16; i++) { v[i] = expf(v[i] - m); s += v[i]; }
#pragma unroll
    for (int o = 16; o; o >>= 1) s += __shfl_xor_sync(0xffffffffu, s, o);
    const float inv = 1.f / s;
#pragma unroll
    for (int i = 0; i < 16; i++) p[lane + (i << 5)] = v[i] * inv;
}

// ---------------- O = P V ----------------
__global__ void __launch_bounds__(256) attn_av(void)
{
    __shared__ float Ps[32][64];
    __shared__ float Vs[32][96];
    const int bh = blockIdx.y, b = bh >> 3, h = bh & 7;
    const int row0 = blockIdx.x * 64;
    const int t = threadIdx.x;
    const int tx = t & 15, ty = t >> 4;
    const int lr = t & 63, lk = (t >> 6) << 3;
    const int kr = t >> 3, cq = (t & 7) * 12;

    const float* Pp = g_scores + (size_t)bh * 262144 + (size_t)(row0 + lr) * 512 + lk;
    const float* Vp = g_qkv + ((size_t)b * 512 + kr) * G3 + 1536 + h * 96 + cq;

    float acc[4][6];
#pragma unroll
    for (int i = 0; i < 4; i++)
#pragma unroll
        for (int j = 0; j < 6; j++) acc[i][j] = 0.f;

    for (int k0 = 0; k0 < 512; k0 += 32) {
        float4 p0 = *(const float4*)(Pp + k0);
        float4 p1 = *(const float4*)(Pp + k0 + 4);
        const float* vp = Vp + (size_t)k0 * G3;
        float4 v0 = *(const float4*)(vp);
        float4 v1 = *(const float4*)(vp + 4);
        float4 v2 = *(const float4*)(vp + 8);
        __syncthreads();
        Ps[lk + 0][lr] = p0.x; Ps[lk + 1][lr] = p0.y; Ps[lk + 2][lr] = p0.z; Ps[lk + 3][lr] = p0.w;
        Ps[lk + 4][lr] = p1.x; Ps[lk + 5][lr] = p1.y; Ps[lk + 6][lr] = p1.z; Ps[lk + 7][lr] = p1.w;
        *(float4*)&Vs[kr][cq + 0] = v0;
        *(float4*)&Vs[kr][cq + 4] = v1;
        *(float4*)&Vs[kr][cq + 8] = v2;
        __syncthreads();
#pragma unroll
        for (int kk = 0; kk < 32; kk++) {
            float a[4];
            *(float4*)a = *(const float4*)&Ps[kk][ty << 2];
            const float* vr = &Vs[kk][tx * 6];
#pragma unroll
            for (int i = 0; i < 4; i++)
#pragma unroll
                for (int j = 0; j < 6; j++)
                    acc[i][j] = fmaf(a[i], vr[j], acc[i][j]);
        }
    }
#pragma unroll
    for (int i = 0; i < 4; i++) {
        size_t r = (size_t)b * 512 + row0 + (ty << 2) + i;
#pragma unroll
        for (int j = 0; j < 6; j++)
            g_att[r * 768 + h * 96 + tx * 6 + j] = acc[i][j];
    }
}

// ---------------- T1: xw [dir][(b*512+s)][G3] -> xwT [dir][s][g][b] ----------------
__global__ void __launch_bounds__(256) xw_transpose(void)
{
    __shared__ float tile[32][65];
    const int g0 = blockIdx.x * 64, s = blockIdx.y, dir = blockIdx.z;
    const int t = threadIdx.x;
    const float* in = g_xw + (size_t)dir * MTOT * G3;
    {
        const int b = t >> 3, q = t & 7;
        const float* src = in + ((size_t)(b * 512 + s)) * G3 + g0 + q * 8;
        float4 v0 = *(const float4*)(src);
        float4 v1 = *(const float4*)(src + 4);
        tile[b][q * 8 + 0] = v0.x; tile[b][q * 8 + 1] = v0.y;
        tile[b][q * 8 + 2] = v0.z; tile[b][q * 8 + 3] = v0.w;
        tile[b][q * 8 + 4] = v1.x; tile[b][q * 8 + 5] = v1.y;
        tile[b][q * 8 + 6] = v1.z; tile[b][q * 8 + 7] = v1.w;
    }
    __syncthreads();
    {
        const int g = t >> 2, bq = (t & 3) * 8;
        float o[8];
#pragma unroll
        for (int j = 0; j < 8; j++) o[j] = tile[bq + j][g];
        float* dst = g_xwT + ((size_t)(dir * 512 + s) * G3 + g0 + g) * 32 + bq;
        *(float4*)(dst)     = make_float4(o[0], o[1], o[2], o[3]);
        *(float4*)(dst + 4) = make_float4(o[4], o[5], o[6], o[7]);
    }
}

// ---------------- T2: hseqT [s][c][b] -> hseq [(b*512+s)][1536] ----------------
__global__ void __launch_bounds__(256) hseq_transpose(float* __restrict__ out)
{
    __shared__ float tile[64][33];
    const int c0 = blockIdx.x * 64, s = blockIdx.y;
    const int t = threadIdx.x;
    {
        const int c = t >> 2, bq = (t & 3) * 8;
        const float* src = g_hseqT + ((size_t)s * 1536 + c0 + c) * 32 + bq;
        float4 v0 = *(const float4*)(src);
        float4 v1 = *(const float4*)(src + 4);
        tile[c][bq + 0] = v0.x; tile[c][bq + 1] = v0.y; tile[c][bq + 2] = v0.z; tile[c][bq + 3] = v0.w;
        tile[c][bq + 4] = v1.x; tile[c][bq + 5] = v1.y; tile[c][bq + 6] = v1.z; tile[c][bq + 7] = v1.w;
    }
    __syncthreads();
    {
        const int b = t >> 3, q = t & 7;
        float o[8];
#pragma unroll
        for (int j = 0; j < 8; j++) o[j] = tile[q * 8 + j][b];
        float* dst = out + ((size_t)(b * 512 + s)) * 1536 + c0 + q * 8;
        *(float4*)(dst)     = make_float4(o[0], o[1], o[2], o[3]);
        *(float4*)(dst + 4) = make_float4(o[4], o[5], o[6], o[7]);
    }
}

// ---------------- reset flags + h ping-pong ----------------
__global__ void gru_reset(void)
{
    int i = blockIdx.x * 256 + threadIdx.x;   // grid 384 x 256 = 98304
    if (i < NBLK) g_flags[i] = 0;
    g_hping[i] = 0.f;
}

// ---------------- persistent GRU layer ----------------
// 128 blocks (64 per dir), 256 threads = 8 warps. Block owns 12 units (36 gate rows).
// lane = batch; warp w handles K-slice [w*96, w*96+96); W kept in smem transposed [k][36].
#define GRU_WS  (36 * 768)
#define GRU_RED (8 * 1152)
#define GRU_SMEM ((GRU_WS + GRU_RED) * 4)

__global__ void __launch_bounds__(256) gru_layer(
    const float* __restrict__ whhF, const float* __restrict__ whhB,
    const float* __restrict__ bhhF, const float* __restrict__ bhhB)
{
    extern __shared__ float sm[];
    float* wsT = sm;                 // [k][36]
    float* red = sm + GRU_WS;        // [warp][36*32]
    __shared__ float bsh[36];

    const int tid = threadIdx.x;
    const int warp = tid >> 5, lane = tid & 31;
    const int blk = blockIdx.x;
    const int dir = blk >> 6, ub = blk & 63;
    const int u0 = ub * 12;
    const float* W   = dir ? whhB : whhF;
    const float* bhh = dir ? bhhB : bhhF;
    const float* xwT = g_xwT + (size_t)dir * 512 * G3 * 32;

    // load W transposed into shared once (rows i = gate*12 + j)
    for (int i = warp; i < 36; i += 8) {
        int gr = (i / 12) * 768 + u0 + (i % 12);
        for (int k = lane; k < 768; k += 32)
            wsT[k * 36 + i] = W[(size_t)gr * 768 + k];
    }
    if (tid < 36) bsh[tid] = bhh[(tid / 12) * 768 + u0 + (tid % 12)];
    __syncthreads();

    const int k0 = warp * 96;

    for (int s = 0; s < 512; s++) {
        if (s > 0) {
            if (tid < NBLK) {
                while (((volatile int*)g_flags)[tid] < s) __nanosleep(32);
            }
            __syncthreads();
            __threadfence();
        }
        const float* hsrc = g_hping + (size_t)(((s & 1) * 2 + dir) * HID) * 32;

        unsigned long long acc2[18];
#pragma unroll
        for (int p = 0; p < 18; p++) acc2[p] = 0ull;

        float hb[4];
#pragma unroll
        for (int q = 0; q < 4; q++) hb[q] = __ldcg(&hsrc[(k0 + q) * 32 + lane]);

        for (int c = 0; c < 24; c++) {
            float hn[4] = {0.f, 0.f, 0.f, 0.f};
            if (c < 23) {
#pragma unroll
                for (int q = 0; q < 4; q++)
                    hn[q] = __ldcg(&hsrc[(k0 + (c + 1) * 4 + q) * 32 + lane]);
            }
#pragma unroll
            for (int q = 0; q < 4; q++) {
                unsigned long long h2 = f2pack(hb[q], hb[q]);
                const float* wrow = &wsT[(k0 + c * 4 + q) * 36];
#pragma unroll
                for (int rq = 0; rq < 9; rq++) {
                    ulonglong2 w2 = *(const ulonglong2*)&wrow[rq * 4];
                    acc2[2 * rq]     = f2fma(w2.x, h2, acc2[2 * rq]);
                    acc2[2 * rq + 1] = f2fma(w2.y, h2, acc2[2 * rq + 1]);
                }
            }
#pragma unroll
            for (int q = 0; q < 4; q++) hb[q] = hn[q];
        }
        // store partials: red[warp][row*32 + lane]
        {
            float* rp = red + warp * 1152;
#pragma unroll
            for (int p = 0; p < 18; p++) {
                float lo, hi;
                f2unpack(acc2[p], lo, hi);
                rp[(2 * p) * 32 + lane]     = lo;
                rp[(2 * p + 1) * 32 + lane] = hi;
            }
        }
        __syncthreads();
        // reduce 8 K-slices
        for (int i = tid; i < 1152; i += 256) {
            float sum = red[i];
#pragma unroll
            for (int w = 1; w < 8; w++) sum += red[w * 1152 + i];
            red[i] = sum;
        }
        __syncthreads();
        // gates
        const int sx = dir ? (511 - s) : s;
        float* hdst = g_hping + (size_t)((((s & 1) ^ 1) * 2 + dir) * HID) * 32;
        const float* xwrow = xwT + (size_t)sx * G3 * 32;
        for (int p = tid; p < 384; p += 256) {
            int j = p >> 5, b = p & 31;
            int ug = u0 + j;
            float xr = xwrow[(size_t)ug * 32 + b];
            float xz = xwrow[(size_t)(768 + ug) * 32 + b];
            float xn = xwrow[(size_t)(1536 + ug) * 32 + b];
            float hr  = red[j * 32 + b]        + bsh[j];
            float hz  = red[(12 + j) * 32 + b] + bsh[12 + j];
            float hn2 = red[(24 + j) * 32 + b] + bsh[24 + j];
            float rr = 1.f / (1.f + expf(-(xr + hr)));
            float zz = 1.f / (1.f + expf(-(xz + hz)));
            float nn = tanhf(xn + rr * hn2);
            float hold = __ldcg(&hsrc[(size_t)ug * 32 + b]);
            float hnew = (1.f - zz) * nn + zz * hold;
            hdst[(size_t)ug * 32 + b] = hnew;
            g_hseqT[((size_t)sx * 1536 + dir * 768 + ug) * 32 + b] = hnew;
        }
        __threadfence();
        __syncthreads();
        if (tid == 0) ((volatile int*)g_flags)[blk] = s + 1;
    }
}

// ---------------- FC: em = h1 @ fc_w^T + fc_b (warp per row, single h pass) ----------------
__global__ void __launch_bounds__(256) fc_kernel(
    const float* __restrict__ h1, const float* __restrict__ fcw,
    const float* __restrict__ fcb)
{
    int warp = threadIdx.x >> 5, lane = threadIdx.x & 31;
    int row = blockIdx.x * 8 + warp;
    const float* hp = h1 + (size_t)row * 1536;
    float s[NC];
#pragma unroll
    for (int c = 0; c < NC; c++) s[c] = 0.f;
    for (int k = lane; k < 1536; k += 32) {
        float hv = hp[k];
#pragma unroll
        for (int c = 0; c < NC; c++) s[c] = fmaf(hv, __ldg(&fcw[c * 1536 + k]), s[c]);
    }
#pragma unroll
    for (int c = 0; c < NC; c++) {
        float v = s[c];
#pragma unroll
        for (int o = 16; o; o >>= 1) v += __shfl_xor_sync(0xffffffffu, v, o);
        if (lane == 0) g_em[(size_t)row * NC + c] = v + fcb[c];
    }
}

// ---------------- CRF NLL (one warp per batch) ----------------
__global__ void crf_nll_kernel(
    const int* __restrict__ labels, const float* __restrict__ start,
    const float* __restrict__ endw, const float* __restrict__ trans)
{
    int b = blockIdx.x;
    int j = threadIdx.x;
    __shared__ float al[2][NC];
    __shared__ float tr[NC * NC];
    for (int i = j; i < NC * NC; i += 32) tr[i] = trans[i];
    const float* e = g_em + (size_t)b * 512 * NC;
    if (j < NC) al[0][j] = start[j] + e[j];
    __syncwarp();
    for (int t = 1; t < 512; t++) {
        int cur = t & 1, prv = cur ^ 1;
        if (j < NC) {
            float m = -1e30f;
#pragma unroll
            for (int i = 0; i < NC; i++) m = fmaxf(m, al[prv][i] + tr[i * NC + j]);
            float s = 0.f;
#pragma unroll
            for (int i = 0; i < NC; i++) s += expf(al[prv][i] + tr[i * NC + j] - m);
            al[cur][j] = m + logf(s) + e[t * NC + j];
        }
        __syncwarp();
    }
    const int* lab = labels + b * 512;
    float acc = 0.f;
    for (int t = j; t < 512; t += 32) acc += e[t * NC + lab[t]];
    for (int t = j; t < 511; t += 32) acc += tr[lab[t] * NC + lab[t + 1]];
#pragma unroll
    for (int o = 16; o; o >>= 1) acc += __shfl_xor_sync(0xffffffffu, acc, o);
    if (j == 0) {
        float m = -1e30f;
#pragma unroll
        for (int jj = 0; jj < NC; jj++) m = fmaxf(m, al[1][jj] + endw[jj]);
        float s = 0.f;
#pragma unroll
        for (int jj = 0; jj < NC; jj++) s += expf(al[1][jj] + endw[jj] - m);
        float denom = m + logf(s);
        float num = acc + start[lab[0]] + endw[lab[511]];
        g_nll[b] = denom - num;
    }
}

__global__ void finalize_loss(float* out)
{
    float s = 0.f;
    for (int i = 0; i < 32; i++) s += g_nll[i];
    out[0] = s;
}

// ---------------- Viterbi (one warp per batch) ----------------
__global__ void viterbi_kernel(
    const float* __restrict__ start, const float* __restrict__ endw,
    const float* __restrict__ trans, float* __restrict__ out)
{
    int b = blockIdx.x;
    int j = threadIdx.x;
    __shared__ float al[2][NC];
    __shared__ float tr[NC * NC];
    __shared__ unsigned char bp[511][NC];
    for (int i = j; i < NC * NC; i += 32) tr[i] = trans[i];
    const float* e = g_em + (size_t)b * 512 * NC;
    if (j < NC) al[0][j] = start[j] + e[j];
    __syncwarp();
    for (int t = 1; t < 512; t++) {
        int cur = t & 1, prv = cur ^ 1;
        if (j < NC) {
            float best = -1e30f;
            int arg = 0;
#pragma unroll
            for (int i = 0; i < NC; i++) {
                float sc = al[prv][i] + tr[i * NC + j];
                if (sc > best) { best = sc; arg = i; }
            }
            al[cur][j] = best + e[t * NC + j];
            bp[t - 1][j] = (unsigned char)arg;
        }
        __syncwarp();
    }
    if (j == 0) {
        float best = -1e30f;
        int last = 0;
#pragma unroll
        for (int jj = 0; jj < NC; jj++) {
            float sc = al[1][jj] + endw[jj];
            if (sc > best) { best = sc; last = jj; }
        }
        float* po = out + 1 + (size_t)b * 512;
        po[511] = (float)last;
        int tag = last;
        for (int t = 510; t >= 0; t--) {
            tag = bp[t][tag];
            po[t] = (float)tag;
        }
    }
}

// ---------------- launch ----------------
extern "C" void kernel_launch(void* const* d_in, const int* in_sizes, int n_in,
                              void* d_out, int out_size)
{
    const float* emb   = (const float*)d_in[0];
    const float* ipw   = (const float*)d_in[1];
    const float* ipb   = (const float*)d_in[2];
    const float* opw   = (const float*)d_in[3];
    const float* opb   = (const float*)d_in[4];
    const float* fcw   = (const float*)d_in[5];
    const float* fcb   = (const float*)d_in[6];
    const float* cstart= (const float*)d_in[7];
    const float* cend  = (const float*)d_in[8];
    const float* ctr   = (const float*)d_in[9];
    const int*   lab   = (const int*)d_in[10];
    const float* wih0f = (const float*)d_in[11];
    const float* whh0f = (const float*)d_in[12];
    const float* bih0f = (const float*)d_in[13];
    const float* bhh0f = (const float*)d_in[14];
    const float* wih0b = (const float*)d_in[15];
    const float* whh0b = (const float*)d_in[16];
    const float* bih0b = (const float*)d_in[17];
    const float* bhh0b = (const float*)d_in[18];
    const float* wih1f = (const float*)d_in[19];
    const float* whh1f = (const float*)d_in[20];
    const float* bih1f = (const float*)d_in[21];
    const float* bhh1f = (const float*)d_in[22];
    const float* wih1b = (const float*)d_in[23];
    const float* whh1b = (const float*)d_in[24];
    const float* bih1b = (const float*)d_in[25];
    const float* bhh1b = (const float*)d_in[26];
    float* out = (float*)d_out;

    static int smem_set = 0;
    if (!smem_set) {
        cudaFuncSetAttribute(gru_layer, cudaFuncAttributeMaxDynamicSharedMemorySize, GRU_SMEM);
        smem_set = 1;
    }

    void* p;
    cudaGetSymbolAddress(&p, g_qkv);  float* qkv = (float*)p;
    cudaGetSymbolAddress(&p, g_att);  float* att = (float*)p;
    cudaGetSymbolAddress(&p, g_x);    float* x   = (float*)p;
    cudaGetSymbolAddress(&p, g_xw);   float* xw  = (float*)p;
    cudaGetSymbolAddress(&p, g_h0);   float* h0  = (float*)p;
    cudaGetSymbolAddress(&p, g_h1);   float* h1  = (float*)p;

    // 1. QKV projection
    sgemm128<<<dim3(G3 / 128, MTOT / 128), 256>>>(emb, ipw, ipb, qkv, MTOT, G3, 768);
    // 2. attention
    attn_scores<<<dim3(8, 8, 256), 256>>>();
    attn_softmax<<<16384, 256>>>();
    attn_av<<<dim3(8, 256), 256>>>();
    // 3. out projection
    sgemm128<<<dim3(768 / 128, MTOT / 128), 256>>>(att, opw, opb, x, MTOT, 768, 768);

    // 4. GRU layers
    for (int l = 0; l < 2; l++) {
        const float* xin  = l ? h0 : x;
        int K             = l ? 1536 : 768;
        const float* wihF = l ? wih1f : wih0f;
        const float* wihB = l ? wih1b : wih0b;
        const float* bihF = l ? bih1f : bih0f;
        const float* bihB = l ? bih1b : bih0b;
        const float* whhF = l ? whh1f : whh0f;
        const float* whhB = l ? whh1b : whh0b;
        const float* bhhF = l ? bhh1f : bhh0f;
        const float* bhhB = l ? bhh1b : bhh0b;
        float* hseq       = l ? h1 : h0;

        sgemm128<<<dim3(G3 / 128, MTOT / 128), 256>>>(xin, wihF, bihF, xw, MTOT, G3, K);
        sgemm128<<<dim3(G3 / 128, MTOT / 128), 256>>>(xin, wihB, bihB, xw + (size_t)MTOT * G3, MTOT, G3, K);
        xw_transpose<<<dim3(36, 512, 2), 256>>>();
        gru_reset<<<384, 256>>>();
        gru_layer<<<NBLK, 256, GRU_SMEM>>>(whhF, whhB, bhhF, bhhB);
        hseq_transpose<<<dim3(24, 512), 256>>>(hseq);
    }

    // 5. FC + CRF + Viterbi
    fc_kernel<<<MTOT / 8, 256>>>(h1, fcw, fcb);
    crf_nll_kernel<<<32, 32>>>(lab, cstart, cend, ctr);
    finalize_loss<<<1, 1>>>(out);
    viterbi_kernel<<<32, 32>>>(cstart, cend, ctr, out);
}

// round 6
// speedup vs baseline: 1.3966x; 1.2067x over previous
#include <cuda_runtime.h>
#include <math.h>

#define MTOT 16384   // B*S
#define G3   2304    // 3*H
#define HID  768
#define NC   9
#define NBLK 128     // persistent GRU blocks

// ---------------- device scratch ----------------
__device__ float g_qkv[(size_t)MTOT * G3];
__device__ float g_scores[(size_t)256 * 512 * 512];
__device__ float g_att[(size_t)MTOT * 768];
__device__ float g_x[(size_t)MTOT * 768];
__device__ float g_xw[(size_t)2 * MTOT * G3];          // [dir][(b*512+s)][G3]
__device__ float g_xwT[(size_t)2 * 512 * G3 * 32];     // [dir][s][g][b]
__device__ float g_hseqT[(size_t)512 * 1536 * 32];     // [s][dir*768+u][b]
__device__ float g_h0[(size_t)MTOT * 1536];
__device__ float g_h1[(size_t)MTOT * 1536];
__device__ float g_hping[2 * 2 * HID * 32];            // [parity][dir][u][b]
__device__ int   g_flags[NBLK];
__device__ float g_em[(size_t)MTOT * NC];
__device__ float g_nll[32];

// ---------------- packed fp32x2 helpers (sm_100+) ----------------
__device__ __forceinline__ unsigned long long f2pack(float lo, float hi) {
    unsigned long long r;
    asm("mov.b64 %0, {%1, %2};" : "=l"(r) : "f"(lo), "f"(hi));
    return r;
}
__device__ __forceinline__ void f2unpack(unsigned long long v, float& lo, float& hi) {
    asm("mov.b64 {%0, %1}, %2;" : "=f"(lo), "=f"(hi) : "l"(v));
}
__device__ __forceinline__ unsigned long long f2fma(unsigned long long a, unsigned long long b, unsigned long long c) {
    unsigned long long d;
    asm("fma.rn.f32x2 %0, %1, %2, %3;" : "=l"(d) : "l"(a), "l"(b), "l"(c));
    return d;
}

// ---------------- tf32 helpers ----------------
__device__ __forceinline__ unsigned cvt_tf32(float v) {
    unsigned r;
    asm("cvt.rna.tf32.f32 %0, %1;" : "=r"(r) : "f"(v));
    return r;
}
__device__ __forceinline__ void mma_tf32(float* c, const unsigned* a, const unsigned* b) {
    asm volatile(
        "mma.sync.aligned.m16n8k8.row.col.f32.tf32.tf32.f32 "
        "{%0,%1,%2,%3}, {%4,%5,%6,%7}, {%8,%9}, {%0,%1,%2,%3};"
        : "+f"(c[0]), "+f"(c[1]), "+f"(c[2]), "+f"(c[3])
        : "r"(a[0]), "r"(a[1]), "r"(a[2]), "r"(a[3]), "r"(b[0]), "r"(b[1]));
}

// ---------------- tf32 tensor-core NT GEMM ----------------
// C[M,N] = A[M,K] @ B[N,K]^T + bias ; M%128==0, N%128==0, K%32==0
// 128x128 block tile, 256 threads (8 warps, 4M x 2N), warp tile 32x64.
// Dynamic smem: As/Bs double-buffered [128][36] uint (tf32 bits); pad 36 makes
// the fragment read pattern (bank = 4g+tg mod 32) conflict-free.
#define TG_BUF 4608           // 128*36
#define TG_SMEM (4 * TG_BUF * 4)  // A(2 bufs) + B(2 bufs), bytes

__global__ void __launch_bounds__(256) tgemm128(
    const float* __restrict__ A, const float* __restrict__ B,
    const float* __restrict__ bias, float* __restrict__ C,
    int M, int N, int K)
{
    extern __shared__ unsigned smu[];
    unsigned* As = smu;               // [2][128][36]
    unsigned* Bs = smu + 2 * TG_BUF;  // [2][128][36]

    const int t = threadIdx.x;
    const int lane = t & 31;
    const int wid = t >> 5;
    const int wm = wid & 3;           // 0..3  (M warps)
    const int wn = wid >> 2;          // 0..1  (N warps)
    const int g  = lane >> 2;         // groupID 0..7
    const int tg = lane & 3;          // thread-in-group 0..3

    const int row0 = blockIdx.y * 128;
    const int col0 = blockIdx.x * 128;

    // global staging mapping: row = t>>1, kslot = (t&1)*16
    const int grow = t >> 1;
    const int gk   = (t & 1) * 16;
    const float* Ap = A + (size_t)(row0 + grow) * K + gk;
    const float* Bp = B + (size_t)(col0 + grow) * K + gk;

    float acc[2][8][4];
#pragma unroll
    for (int mt = 0; mt < 2; mt++)
#pragma unroll
        for (int nt = 0; nt < 8; nt++)
#pragma unroll
            for (int q = 0; q < 4; q++) acc[mt][nt][q] = 0.f;

    // prologue: load chunk 0 into buf 0
    {
#pragma unroll
        for (int j = 0; j < 4; j++) {
            float4 va = *(const float4*)(Ap + j * 4);
            float4 vb = *(const float4*)(Bp + j * 4);
            unsigned* da = &As[grow * 36 + gk + j * 4];
            unsigned* db = &Bs[grow * 36 + gk + j * 4];
            da[0] = cvt_tf32(va.x); da[1] = cvt_tf32(va.y);
            da[2] = cvt_tf32(va.z); da[3] = cvt_tf32(va.w);
            db[0] = cvt_tf32(vb.x); db[1] = cvt_tf32(vb.y);
            db[2] = cvt_tf32(vb.z); db[3] = cvt_tf32(vb.w);
        }
    }
    __syncthreads();

    int cur = 0;
    for (int kt = 0; kt < K; kt += 32) {
        const bool more = (kt + 32) < K;
        float4 sa[4], sb[4];
        if (more) {
#pragma unroll
            for (int j = 0; j < 4; j++) {
                sa[j] = *(const float4*)(Ap + kt + 32 + j * 4);
                sb[j] = *(const float4*)(Bp + kt + 32 + j * 4);
            }
        }
        // compute on buf cur
        const unsigned* Ab = As + cur * TG_BUF;
        const unsigned* Bb = Bs + cur * TG_BUF;
#pragma unroll
        for (int ks = 0; ks < 4; ks++) {
            const int kk = ks * 8;
            unsigned af[2][4];
#pragma unroll
            for (int mt = 0; mt < 2; mt++) {
                const int r = wm * 32 + mt * 16 + g;
                af[mt][0] = Ab[(r)     * 36 + kk + tg];
                af[mt][1] = Ab[(r + 8) * 36 + kk + tg];
                af[mt][2] = Ab[(r)     * 36 + kk + tg + 4];
                af[mt][3] = Ab[(r + 8) * 36 + kk + tg + 4];
            }
            unsigned bf[8][2];
#pragma unroll
            for (int nt = 0; nt < 8; nt++) {
                const int n = wn * 64 + nt * 8 + g;
                bf[nt][0] = Bb[n * 36 + kk + tg];
                bf[nt][1] = Bb[n * 36 + kk + tg + 4];
            }
#pragma unroll
            for (int mt = 0; mt < 2; mt++)
#pragma unroll
                for (int nt = 0; nt < 8; nt++)
                    mma_tf32(acc[mt][nt], af[mt], bf[nt]);
        }
        if (more) {
            const int nxt = cur ^ 1;
            unsigned* da = &As[nxt * TG_BUF + grow * 36 + gk];
            unsigned* db = &Bs[nxt * TG_BUF + grow * 36 + gk];
#pragma unroll
            for (int j = 0; j < 4; j++) {
                da[j * 4 + 0] = cvt_tf32(sa[j].x); da[j * 4 + 1] = cvt_tf32(sa[j].y);
                da[j * 4 + 2] = cvt_tf32(sa[j].z); da[j * 4 + 3] = cvt_tf32(sa[j].w);
                db[j * 4 + 0] = cvt_tf32(sb[j].x); db[j * 4 + 1] = cvt_tf32(sb[j].y);
                db[j * 4 + 2] = cvt_tf32(sb[j].z); db[j * 4 + 3] = cvt_tf32(sb[j].w);
            }
            __syncthreads();
            cur = nxt;
        }
    }

    // epilogue: bias + store
#pragma unroll
    for (int mt = 0; mt < 2; mt++) {
        const int r = row0 + wm * 32 + mt * 16 + g;
#pragma unroll
        for (int nt = 0; nt < 8; nt++) {
            const int c = col0 + wn * 64 + nt * 8 + 2 * tg;
            const float b0 = bias[c], b1 = bias[c + 1];
            float2 v0 = make_float2(acc[mt][nt][0] + b0, acc[mt][nt][1] + b1);
            float2 v1 = make_float2(acc[mt][nt][2] + b0, acc[mt][nt][3] + b1);
            *(float2*)&C[(size_t)r * N + c]       = v0;
            *(float2*)&C[(size_t)(r + 8) * N + c] = v1;
        }
    }
}

// ---------------- attention scores = scale * Q K^T ----------------
__global__ void __launch_bounds__(256) attn_scores(void)
{
    __shared__ float Qs[16][64];
    __shared__ float Ks[16][64];
    const int bh = blockIdx.z, b = bh >> 3, h = bh & 7;
    const int row0 = blockIdx.y * 64, col0 = blockIdx.x * 64;
    const int t = threadIdx.x;
    const int lr = t & 63, lk = (t >> 6) << 2;
    const int tx = t & 15, ty = t >> 4;

    const float* Qp = g_qkv + ((size_t)b * 512 + row0 + lr) * G3 + h * 96 + lk;
    const float* Kp = g_qkv + ((size_t)b * 512 + col0 + lr) * G3 + 768 + h * 96 + lk;

    float acc[4][4];
#pragma unroll
    for (int i = 0; i < 4; i++)
#pragma unroll
        for (int j = 0; j < 4; j++) acc[i][j] = 0.f;

    for (int k0 = 0; k0 < 96; k0 += 16) {
        float4 qv = *(const float4*)(Qp + k0);
        float4 kv = *(const float4*)(Kp + k0);
        __syncthreads();
        Qs[lk + 0][lr] = qv.x; Qs[lk + 1][lr] = qv.y; Qs[lk + 2][lr] = qv.z; Qs[lk + 3][lr] = qv.w;
        Ks[lk + 0][lr] = kv.x; Ks[lk + 1][lr] = kv.y; Ks[lk + 2][lr] = kv.z; Ks[lk + 3][lr] = kv.w;
        __syncthreads();
#pragma unroll
        for (int kk = 0; kk < 16; kk++) {
            float a[4], c[4];
            *(float4*)a = *(const float4*)&Qs[kk][ty << 2];
            *(float4*)c = *(const float4*)&Ks[kk][tx << 2];
#pragma unroll
            for (int i = 0; i < 4; i++)
#pragma unroll
                for (int j = 0; j < 4; j++)
                    acc[i][j] = fmaf(a[i], c[j], acc[i][j]);
        }
    }
    const float scale = 0.1020620726159657f; // 1/sqrt(96)
    float* Cb = g_scores + (size_t)bh * 262144;
#pragma unroll
    for (int i = 0; i < 4; i++)
#pragma unroll
        for (int j = 0; j < 4; j++)
            Cb[(size_t)(row0 + (ty << 2) + i) * 512 + col0 + (tx << 2) + j] = acc[i][j] * scale;
}

// ---------------- softmax over rows of 512 (warp per row) ----------------
__global__ void __launch_bounds__(256) attn_softmax(void)
{
    const int warp = threadIdx.x >> 5, lane = threadIdx.x & 31;
    const size_t row = (size_t)blockIdx.x * 8 + warp;
    float* p = g_scores + row * 512;
    float v[16];
    float m = -1e30f;
#pragma unroll
    for (int i = 0; i < 16; i++) { v[i] = p[lane + (i << 5)]; m = fmaxf(m, v[i]); }
#pragma unroll
    for (int o = 16; o; o >>= 1) m = fmaxf(m, __shfl_xor_sync(0xffffffffu, m, o));
    float s = 0.f;
#pragma unroll
    for (int i = 0; i < 16; i++) { v[i] = expf(v[i] - m); s += v[i]; }
#pragma unroll
    for (int o = 16; o; o >>= 1) s += __shfl_xor_sync(0xffffffffu, s, o);
    const float inv = 1.f / s;
#pragma unroll
    for (int i = 0; i < 16; i++) p[lane + (i << 5)] = v[i] * inv;
}

// ---------------- O = P V ----------------
__global__ void __launch_bounds__(256) attn_av(void)
{
    __shared__ float Ps[32][64];
    __shared__ float Vs[32][96];
    const int bh = blockIdx.y, b = bh >> 3, h = bh & 7;
    const int row0 = blockIdx.x * 64;
    const int t = threadIdx.x;
    const int tx = t & 15, ty = t >> 4;
    const int lr = t & 63, lk = (t >> 6) << 3;
    const int kr = t >> 3, cq = (t & 7) * 12;

    const float* Pp = g_scores + (size_t)bh * 262144 + (size_t)(row0 + lr) * 512 + lk;
    const float* Vp = g_qkv + ((size_t)b * 512 + kr) * G3 + 1536 + h * 96 + cq;

    float acc[4][6];
#pragma unroll
    for (int i = 0; i < 4; i++)
#pragma unroll
        for (int j = 0; j < 6; j++) acc[i][j] = 0.f;

    for (int k0 = 0; k0 < 512; k0 += 32) {
        float4 p0 = *(const float4*)(Pp + k0);
        float4 p1 = *(const float4*)(Pp + k0 + 4);
        const float* vp = Vp + (size_t)k0 * G3;
        float4 v0 = *(const float4*)(vp);
        float4 v1 = *(const float4*)(vp + 4);
        float4 v2 = *(const float4*)(vp + 8);
        __syncthreads();
        Ps[lk + 0][lr] = p0.x; Ps[lk + 1][lr] = p0.y; Ps[lk + 2][lr] = p0.z; Ps[lk + 3][lr] = p0.w;
        Ps[lk + 4][lr] = p1.x; Ps[lk + 5][lr] = p1.y; Ps[lk + 6][lr] = p1.z; Ps[lk + 7][lr] = p1.w;
        *(float4*)&Vs[kr][cq + 0] = v0;
        *(float4*)&Vs[kr][cq + 4] = v1;
        *(float4*)&Vs[kr][cq + 8] = v2;
        __syncthreads();
#pragma unroll
        for (int kk = 0; kk < 32; kk++) {
            float a[4];
            *(float4*)a = *(const float4*)&Ps[kk][ty << 2];
            const float* vr = &Vs[kk][tx * 6];
#pragma unroll
            for (int i = 0; i < 4; i++)
#pragma unroll
                for (int j = 0; j < 6; j++)
                    acc[i][j] = fmaf(a[i], vr[j], acc[i][j]);
        }
    }
#pragma unroll
    for (int i = 0; i < 4; i++) {
        size_t r = (size_t)b * 512 + row0 + (ty << 2) + i;
#pragma unroll
        for (int j = 0; j < 6; j++)
            g_att[r * 768 + h * 96 + tx * 6 + j] = acc[i][j];
    }
}

// ---------------- T1: xw [dir][(b*512+s)][G3] -> xwT [dir][s][g][b] ----------------
__global__ void __launch_bounds__(256) xw_transpose(void)
{
    __shared__ float tile[32][65];
    const int g0 = blockIdx.x * 64, s = blockIdx.y, dir = blockIdx.z;
    const int t = threadIdx.x;
    const float* in = g_xw + (size_t)dir * MTOT * G3;
    {
        const int b = t >> 3, q = t & 7;
        const float* src = in + ((size_t)(b * 512 + s)) * G3 + g0 + q * 8;
        float4 v0 = *(const float4*)(src);
        float4 v1 = *(const float4*)(src + 4);
        tile[b][q * 8 + 0] = v0.x; tile[b][q * 8 + 1] = v0.y;
        tile[b][q * 8 + 2] = v0.z; tile[b][q * 8 + 3] = v0.w;
        tile[b][q * 8 + 4] = v1.x; tile[b][q * 8 + 5] = v1.y;
        tile[b][q * 8 + 6] = v1.z; tile[b][q * 8 + 7] = v1.w;
    }
    __syncthreads();
    {
        const int g = t >> 2, bq = (t & 3) * 8;
        float o[8];
#pragma unroll
        for (int j = 0; j < 8; j++) o[j] = tile[bq + j][g];
        float* dst = g_xwT + ((size_t)(dir * 512 + s) * G3 + g0 + g) * 32 + bq;
        *(float4*)(dst)     = make_float4(o[0], o[1], o[2], o[3]);
        *(float4*)(dst + 4) = make_float4(o[4], o[5], o[6], o[7]);
    }
}

// ---------------- T2: hseqT [s][c][b] -> hseq [(b*512+s)][1536] ----------------
__global__ void __launch_bounds__(256) hseq_transpose(float* __restrict__ out)
{
    __shared__ float tile[64][33];
    const int c0 = blockIdx.x * 64, s = blockIdx.y;
    const int t = threadIdx.x;
    {
        const int c = t >> 2, bq = (t & 3) * 8;
        const float* src = g_hseqT + ((size_t)s * 1536 + c0 + c) * 32 + bq;
        float4 v0 = *(const float4*)(src);
        float4 v1 = *(const float4*)(src + 4);
        tile[c][bq + 0] = v0.x; tile[c][bq + 1] = v0.y; tile[c][bq + 2] = v0.z; tile[c][bq + 3] = v0.w;
        tile[c][bq + 4] = v1.x; tile[c][bq + 5] = v1.y; tile[c][bq + 6] = v1.z; tile[c][bq + 7] = v1.w;
    }
    __syncthreads();
    {
        const int b = t >> 3, q = t & 7;
        float o[8];
#pragma unroll
        for (int j = 0; j < 8; j++) o[j] = tile[q * 8 + j][b];
        float* dst = out + ((size_t)(b * 512 + s)) * 1536 + c0 + q * 8;
        *(float4*)(dst)     = make_float4(o[0], o[1], o[2], o[3]);
        *(float4*)(dst + 4) = make_float4(o[4], o[5], o[6], o[7]);
    }
}

// ---------------- reset flags + h ping-pong ----------------
__global__ void gru_reset(void)
{
    int i = blockIdx.x * 256 + threadIdx.x;   // grid 384 x 256 = 98304
    if (i < NBLK) g_flags[i] = 0;
    g_hping[i] = 0.f;
}

// ---------------- persistent GRU layer ----------------
#define GRU_WS  (36 * 768)
#define GRU_RED (8 * 1152)
#define GRU_SMEM ((GRU_WS + GRU_RED) * 4)

__global__ void __launch_bounds__(256) gru_layer(
    const float* __restrict__ whhF, const float* __restrict__ whhB,
    const float* __restrict__ bhhF, const float* __restrict__ bhhB)
{
    extern __shared__ float sm[];
    float* wsT = sm;                 // [k][36]
    float* red = sm + GRU_WS;        // [warp][36*32]
    __shared__ float bsh[36];

    const int tid = threadIdx.x;
    const int warp = tid >> 5, lane = tid & 31;
    const int blk = blockIdx.x;
    const int dir = blk >> 6, ub = blk & 63;
    const int u0 = ub * 12;
    const float* W   = dir ? whhB : whhF;
    const float* bhh = dir ? bhhB : bhhF;
    const float* xwT = g_xwT + (size_t)dir * 512 * G3 * 32;

    for (int i = warp; i < 36; i += 8) {
        int gr = (i / 12) * 768 + u0 + (i % 12);
        for (int k = lane; k < 768; k += 32)
            wsT[k * 36 + i] = W[(size_t)gr * 768 + k];
    }
    if (tid < 36) bsh[tid] = bhh[(tid / 12) * 768 + u0 + (tid % 12)];
    __syncthreads();

    const int k0 = warp * 96;

    for (int s = 0; s < 512; s++) {
        if (s > 0) {
            if (tid < NBLK) {
                while (((volatile int*)g_flags)[tid] < s) __nanosleep(32);
            }
            __syncthreads();
            __threadfence();
        }
        const float* hsrc = g_hping + (size_t)(((s & 1) * 2 + dir) * HID) * 32;

        unsigned long long acc2[18];
#pragma unroll
        for (int p = 0; p < 18; p++) acc2[p] = 0ull;

        float hb[4];
#pragma unroll
        for (int q = 0; q < 4; q++) hb[q] = __ldcg(&hsrc[(k0 + q) * 32 + lane]);

        for (int c = 0; c < 24; c++) {
            float hn[4] = {0.f, 0.f, 0.f, 0.f};
            if (c < 23) {
#pragma unroll
                for (int q = 0; q < 4; q++)
                    hn[q] = __ldcg(&hsrc[(k0 + (c + 1) * 4 + q) * 32 + lane]);
            }
#pragma unroll
            for (int q = 0; q < 4; q++) {
                unsigned long long h2 = f2pack(hb[q], hb[q]);
                const float* wrow = &wsT[(k0 + c * 4 + q) * 36];
#pragma unroll
                for (int rq = 0; rq < 9; rq++) {
                    ulonglong2 w2 = *(const ulonglong2*)&wrow[rq * 4];
                    acc2[2 * rq]     = f2fma(w2.x, h2, acc2[2 * rq]);
                    acc2[2 * rq + 1] = f2fma(w2.y, h2, acc2[2 * rq + 1]);
                }
            }
#pragma unroll
            for (int q = 0; q < 4; q++) hb[q] = hn[q];
        }
        {
            float* rp = red + warp * 1152;
#pragma unroll
            for (int p = 0; p < 18; p++) {
                float lo, hi;
                f2unpack(acc2[p], lo, hi);
                rp[(2 * p) * 32 + lane]     = lo;
                rp[(2 * p + 1) * 32 + lane] = hi;
            }
        }
        __syncthreads();
        for (int i = tid; i < 1152; i += 256) {
            float sum = red[i];
#pragma unroll
            for (int w = 1; w < 8; w++) sum += red[w * 1152 + i];
            red[i] = sum;
        }
        __syncthreads();
        const int sx = dir ? (511 - s) : s;
        float* hdst = g_hping + (size_t)((((s & 1) ^ 1) * 2 + dir) * HID) * 32;
        const float* xwrow = xwT + (size_t)sx * G3 * 32;
        for (int p = tid; p < 384; p += 256) {
            int j = p >> 5, b = p & 31;
            int ug = u0 + j;
            float xr = xwrow[(size_t)ug * 32 + b];
            float xz = xwrow[(size_t)(768 + ug) * 32 + b];
            float xn = xwrow[(size_t)(1536 + ug) * 32 + b];
            float hr  = red[j * 32 + b]        + bsh[j];
            float hz  = red[(12 + j) * 32 + b] + bsh[12 + j];
            float hn2 = red[(24 + j) * 32 + b] + bsh[24 + j];
            float rr = 1.f / (1.f + expf(-(xr + hr)));
            float zz = 1.f / (1.f + expf(-(xz + hz)));
            float nn = tanhf(xn + rr * hn2);
            float hold = __ldcg(&hsrc[(size_t)ug * 32 + b]);
            float hnew = (1.f - zz) * nn + zz * hold;
            hdst[(size_t)ug * 32 + b] = hnew;
            g_hseqT[((size_t)sx * 1536 + dir * 768 + ug) * 32 + b] = hnew;
        }
        __threadfence();
        __syncthreads();
        if (tid == 0) ((volatile int*)g_flags)[blk] = s + 1;
    }
}

// ---------------- FC: em = h1 @ fc_w^T + fc_b ----------------
__global__ void __launch_bounds__(256) fc_kernel(
    const float* __restrict__ h1, const float* __restrict__ fcw,
    const float* __restrict__ fcb)
{
    int warp = threadIdx.x >> 5, lane = threadIdx.x & 31;
    int row = blockIdx.x * 8 + warp;
    const float* hp = h1 + (size_t)row * 1536;
    float s[NC];
#pragma unroll
    for (int c = 0; c < NC; c++) s[c] = 0.f;
    for (int k = lane; k < 1536; k += 32) {
        float hv = hp[k];
#pragma unroll
        for (int c = 0; c < NC; c++) s[c] = fmaf(hv, __ldg(&fcw[c * 1536 + k]), s[c]);
    }
#pragma unroll
    for (int c = 0; c < NC; c++) {
        float v = s[c];
#pragma unroll
        for (int o = 16; o; o >>= 1) v += __shfl_xor_sync(0xffffffffu, v, o);
        if (lane == 0) g_em[(size_t)row * NC + c] = v + fcb[c];
    }
}

// ---------------- CRF NLL (one warp per batch) ----------------
__global__ void crf_nll_kernel(
    const int* __restrict__ labels, const float* __restrict__ start,
    const float* __restrict__ endw, const float* __restrict__ trans)
{
    int b = blockIdx.x;
    int j = threadIdx.x;
    __shared__ float al[2][NC];
    __shared__ float tr[NC * NC];
    for (int i = j; i < NC * NC; i += 32) tr[i] = trans[i];
    const float* e = g_em + (size_t)b * 512 * NC;
    if (j < NC) al[0][j] = start[j] + e[j];
    __syncwarp();
    for (int t = 1; t < 512; t++) {
        int cur = t & 1, prv = cur ^ 1;
        if (j < NC) {
            float m = -1e30f;
#pragma unroll
            for (int i = 0; i < NC; i++) m = fmaxf(m, al[prv][i] + tr[i * NC + j]);
            float s = 0.f;
#pragma unroll
            for (int i = 0; i < NC; i++) s += expf(al[prv][i] + tr[i * NC + j] - m);
            al[cur][j] = m + logf(s) + e[t * NC + j];
        }
        __syncwarp();
    }
    const int* lab = labels + b * 512;
    float acc = 0.f;
    for (int t = j; t < 512; t += 32) acc += e[t * NC + lab[t]];
    for (int t = j; t < 511; t += 32) acc += tr[lab[t] * NC + lab[t + 1]];
#pragma unroll
    for (int o = 16; o; o >>= 1) acc += __shfl_xor_sync(0xffffffffu, acc, o);
    if (j == 0) {
        float m = -1e30f;
#pragma unroll
        for (int jj = 0; jj < NC; jj++) m = fmaxf(m, al[1][jj] + endw[jj]);
        float s = 0.f;
#pragma unroll
        for (int jj = 0; jj < NC; jj++) s += expf(al[1][jj] + endw[jj] - m);
        float denom = m + logf(s);
        float num = acc + start[lab[0]] + endw[lab[511]];
        g_nll[b] = denom - num;
    }
}

__global__ void finalize_loss(float* out)
{
    float s = 0.f;
    for (int i = 0; i < 32; i++) s += g_nll[i];
    out[0] = s;
}

// ---------------- Viterbi (one warp per batch) ----------------
__global__ void viterbi_kernel(
    const float* __restrict__ start, const float* __restrict__ endw,
    const float* __restrict__ trans, float* __restrict__ out)
{
    int b = blockIdx.x;
    int j = threadIdx.x;
    __shared__ float al[2][NC];
    __shared__ float tr[NC * NC];
    __shared__ unsigned char bp[511][NC];
    for (int i = j; i < NC * NC; i += 32) tr[i] = trans[i];
    const float* e = g_em + (size_t)b * 512 * NC;
    if (j < NC) al[0][j] = start[j] + e[j];
    __syncwarp();
    for (int t = 1; t < 512; t++) {
        int cur = t & 1, prv = cur ^ 1;
        if (j < NC) {
            float best = -1e30f;
            int arg = 0;
#pragma unroll
            for (int i = 0; i < NC; i++) {
                float sc = al[prv][i] + tr[i * NC + j];
                if (sc > best) { best = sc; arg = i; }
            }
            al[cur][j] = best + e[t * NC + j];
            bp[t - 1][j] = (unsigned char)arg;
        }
        __syncwarp();
    }
    if (j == 0) {
        float best = -1e30f;
        int last = 0;
#pragma unroll
        for (int jj = 0; jj < NC; jj++) {
            float sc = al[1][jj] + endw[jj];
            if (sc > best) { best = sc; last = jj; }
        }
        float* po = out + 1 + (size_t)b * 512;
        po[511] = (float)last;
        int tag = last;
        for (int t = 510; t >= 0; t--) {
            tag = bp[t][tag];
            po[t] = (float)tag;
        }
    }
}

// ---------------- launch ----------------
extern "C" void kernel_launch(void* const* d_in, const int* in_sizes, int n_in,
                              void* d_out, int out_size)
{
    const float* emb   = (const float*)d_in[0];
    const float* ipw   = (const float*)d_in[1];
    const float* ipb   = (const float*)d_in[2];
    const float* opw   = (const float*)d_in[3];
    const float* opb   = (const float*)d_in[4];
    const float* fcw   = (const float*)d_in[5];
    const float* fcb   = (const float*)d_in[6];
    const float* cstart= (const float*)d_in[7];
    const float* cend  = (const float*)d_in[8];
    const float* ctr   = (const float*)d_in[9];
    const int*   lab   = (const int*)d_in[10];
    const float* wih0f = (const float*)d_in[11];
    const float* whh0f = (const float*)d_in[12];
    const float* bih0f = (const float*)d_in[13];
    const float* bhh0f = (const float*)d_in[14];
    const float* wih0b = (const float*)d_in[15];
    const float* whh0b = (const float*)d_in[16];
    const float* bih0b = (const float*)d_in[17];
    const float* bhh0b = (const float*)d_in[18];
    const float* wih1f = (const float*)d_in[19];
    const float* whh1f = (const float*)d_in[20];
    const float* bih1f = (const float*)d_in[21];
    const float* bhh1f = (const float*)d_in[22];
    const float* wih1b = (const float*)d_in[23];
    const float* whh1b = (const float*)d_in[24];
    const float* bih1b = (const float*)d_in[25];
    const float* bhh1b = (const float*)d_in[26];
    float* out = (float*)d_out;

    static int attr_set = 0;
    if (!attr_set) {
        cudaFuncSetAttribute(gru_layer, cudaFuncAttributeMaxDynamicSharedMemorySize, GRU_SMEM);
        cudaFuncSetAttribute(tgemm128, cudaFuncAttributeMaxDynamicSharedMemorySize, TG_SMEM);
        attr_set = 1;
    }

    void* p;
    cudaGetSymbolAddress(&p, g_qkv);  float* qkv = (float*)p;
    cudaGetSymbolAddress(&p, g_att);  float* att = (float*)p;
    cudaGetSymbolAddress(&p, g_x);    float* x   = (float*)p;
    cudaGetSymbolAddress(&p, g_xw);   float* xw  = (float*)p;
    cudaGetSymbolAddress(&p, g_h0);   float* h0  = (float*)p;
    cudaGetSymbolAddress(&p, g_h1);   float* h1  = (float*)p;

    // 1. QKV projection
    tgemm128<<<dim3(G3 / 128, MTOT / 128), 256, TG_SMEM>>>(emb, ipw, ipb, qkv, MTOT, G3, 768);
    // 2. attention
    attn_scores<<<dim3(8, 8, 256), 256>>>();
    attn_softmax<<<16384, 256>>>();
    attn_av<<<dim3(8, 256), 256>>>();
    // 3. out projection
    tgemm128<<<dim3(768 / 128, MTOT / 128), 256, TG_SMEM>>>(att, opw, opb, x, MTOT, 768, 768);

    // 4. GRU layers
    for (int l = 0; l < 2; l++) {
        const float* xin  = l ? h0 : x;
        int K             = l ? 1536 : 768;
        const float* wihF = l ? wih1f : wih0f;
        const float* wihB = l ? wih1b : wih0b;
        const float* bihF = l ? bih1f : bih0f;
        const float* bihB = l ? bih1b : bih0b;
        const float* whhF = l ? whh1f : whh0f;
        const float* whhB = l ? whh1b : whh0b;
        const float* bhhF = l ? bhh1f : bhh0f;
        const float* bhhB = l ? bhh1b : bhh0b;
        float* hseq       = l ? h1 : h0;

        tgemm128<<<dim3(G3 / 128, MTOT / 128), 256, TG_SMEM>>>(xin, wihF, bihF, xw, MTOT, G3, K);
        tgemm128<<<dim3(G3 / 128, MTOT / 128), 256, TG_SMEM>>>(xin, wihB, bihB, xw + (size_t)MTOT * G3, MTOT, G3, K);
        xw_transpose<<<dim3(36, 512, 2), 256>>>();
        gru_reset<<<384, 256>>>();
        gru_layer<<<NBLK, 256, GRU_SMEM>>>(whhF, whhB, bhhF, bhhB);
        hseq_transpose<<<dim3(24, 512), 256>>>(hseq);
    }

    // 5. FC + CRF + Viterbi
    fc_kernel<<<MTOT / 8, 256>>>(h1, fcw, fcb);
    crf_nll_kernel<<<32, 32>>>(lab, cstart, cend, ctr);
    finalize_loss<<<1, 1>>>(out);
    viterbi_kernel<<<32, 32>>>(cstart, cend, ctr, out);
}

// round 7
// speedup vs baseline: 2.2847x; 1.6359x over previous
#include <cuda_runtime.h>
#include <math.h>

#define MTOT 16384   // B*S
#define G3   2304    // 3*H
#define HID  768
#define NC   9
#define GNB  96      // persistent GRU blocks (48 per dir)

// ---------------- device scratch ----------------
__device__ float g_qkv[(size_t)MTOT * G3];
__device__ float g_scores[(size_t)256 * 512 * 512];
__device__ float g_att[(size_t)MTOT * 768];
__device__ float g_x[(size_t)MTOT * 768];
__device__ float g_xwT[(size_t)2 * 512 * 32 * G3];     // [dir][s][b][G3]
__device__ float g_hseqT[(size_t)512 * 2 * 32 * 768];  // [s][dir][b][u]
__device__ float g_hping[2 * 2 * 32 * HID];            // [parity][dir][b][u]
__device__ int   g_flags[GNB];
__device__ float g_em[(size_t)MTOT * NC];
__device__ float g_nll[32];

// ---------------- tf32 helpers ----------------
__device__ __forceinline__ unsigned cvt_tf32(float v) {
    unsigned r;
    asm("cvt.rna.tf32.f32 %0, %1;" : "=r"(r) : "f"(v));
    return r;
}
__device__ __forceinline__ void mma_tf32(float* c, const unsigned* a, const unsigned* b) {
    asm volatile(
        "mma.sync.aligned.m16n8k8.row.col.f32.tf32.tf32.f32 "
        "{%0,%1,%2,%3}, {%4,%5,%6,%7}, {%8,%9}, {%0,%1,%2,%3};"
        : "+f"(c[0]), "+f"(c[1]), "+f"(c[2]), "+f"(c[3])
        : "r"(a[0]), "r"(a[1]), "r"(a[2]), "r"(a[3]), "r"(b[0]), "r"(b[1]));
}

// ---------------- tf32 tensor-core NT GEMM ----------------
// C[M,N] = A[M,K] @ B[N,K]^T + bias ; M%128==0, N%128==0, K%32==0
// gatherA: A row r=(b*512+s), element k -> g_hseqT layout [s][dir][b][u]
// permC:   C row r=(b*512+s) stored at row' = s*32+b (into xwT [s][b][N])
#define TG_BUF 4608               // 128*36
#define TG_SMEM (4 * TG_BUF * 4)

__global__ void __launch_bounds__(256) tgemm128(
    const float* __restrict__ A, const float* __restrict__ B,
    const float* __restrict__ bias, float* __restrict__ C,
    int M, int N, int K, int gatherA, int permC)
{
    extern __shared__ unsigned smu[];
    unsigned* As = smu;               // [2][128][36]
    unsigned* Bs = smu + 2 * TG_BUF;  // [2][128][36]

    const int t = threadIdx.x;
    const int lane = t & 31;
    const int wid = t >> 5;
    const int wm = wid & 3;
    const int wn = wid >> 2;
    const int g  = lane >> 2;
    const int tg = lane & 3;

    const int row0 = blockIdx.y * 128;
    const int col0 = blockIdx.x * 128;

    const int grow = t >> 1;
    const int gk   = (t & 1) * 16;
    const int rowA = row0 + grow;

    size_t gb0 = 0, gb1 = 0;
    const float* Ap = A + (size_t)rowA * K + gk;
    if (gatherA) {
        int bb = rowA >> 9, sq = rowA & 511;
        gb0 = ((size_t)(sq * 2) * 32 + bb) * 768;
        gb1 = ((size_t)(sq * 2 + 1) * 32 + bb) * 768;
    }
    const float* Bp = B + (size_t)(col0 + grow) * K + gk;

    float acc[2][8][4];
#pragma unroll
    for (int mt = 0; mt < 2; mt++)
#pragma unroll
        for (int nt = 0; nt < 8; nt++)
#pragma unroll
            for (int q = 0; q < 4; q++) acc[mt][nt][q] = 0.f;

    // prologue chunk 0
    {
        const float* ApC = gatherA ? (A + (gk < 768 ? gb0 + gk : gb1 + gk - 768)) : Ap;
#pragma unroll
        for (int j = 0; j < 4; j++) {
            float4 va = *(const float4*)(ApC + j * 4);
            float4 vb = *(const float4*)(Bp + j * 4);
            unsigned* da = &As[grow * 36 + gk + j * 4];
            unsigned* db = &Bs[grow * 36 + gk + j * 4];
            da[0] = cvt_tf32(va.x); da[1] = cvt_tf32(va.y);
            da[2] = cvt_tf32(va.z); da[3] = cvt_tf32(va.w);
            db[0] = cvt_tf32(vb.x); db[1] = cvt_tf32(vb.y);
            db[2] = cvt_tf32(vb.z); db[3] = cvt_tf32(vb.w);
        }
    }
    __syncthreads();

    int cur = 0;
    for (int kt = 0; kt < K; kt += 32) {
        const bool more = (kt + 32) < K;
        float4 sa[4], sb[4];
        if (more) {
            const int o = kt + 32 + gk;
            const float* ApC = gatherA ? (A + (o < 768 ? gb0 + o : gb1 + o - 768)) : (Ap + kt + 32);
#pragma unroll
            for (int j = 0; j < 4; j++) {
                sa[j] = *(const float4*)(ApC + j * 4);
                sb[j] = *(const float4*)(Bp + kt + 32 + j * 4);
            }
        }
        const unsigned* Ab = As + cur * TG_BUF;
        const unsigned* Bb = Bs + cur * TG_BUF;
#pragma unroll
        for (int ks = 0; ks < 4; ks++) {
            const int kk = ks * 8;
            unsigned af[2][4];
#pragma unroll
            for (int mt = 0; mt < 2; mt++) {
                const int r = wm * 32 + mt * 16 + g;
                af[mt][0] = Ab[(r)     * 36 + kk + tg];
                af[mt][1] = Ab[(r + 8) * 36 + kk + tg];
                af[mt][2] = Ab[(r)     * 36 + kk + tg + 4];
                af[mt][3] = Ab[(r + 8) * 36 + kk + tg + 4];
            }
            unsigned bf[8][2];
#pragma unroll
            for (int nt = 0; nt < 8; nt++) {
                const int n = wn * 64 + nt * 8 + g;
                bf[nt][0] = Bb[n * 36 + kk + tg];
                bf[nt][1] = Bb[n * 36 + kk + tg + 4];
            }
#pragma unroll
            for (int mt = 0; mt < 2; mt++)
#pragma unroll
                for (int nt = 0; nt < 8; nt++)
                    mma_tf32(acc[mt][nt], af[mt], bf[nt]);
        }
        if (more) {
            const int nxt = cur ^ 1;
            unsigned* da = &As[nxt * TG_BUF + grow * 36 + gk];
            unsigned* db = &Bs[nxt * TG_BUF + grow * 36 + gk];
#pragma unroll
            for (int j = 0; j < 4; j++) {
                da[j * 4 + 0] = cvt_tf32(sa[j].x); da[j * 4 + 1] = cvt_tf32(sa[j].y);
                da[j * 4 + 2] = cvt_tf32(sa[j].z); da[j * 4 + 3] = cvt_tf32(sa[j].w);
                db[j * 4 + 0] = cvt_tf32(sb[j].x); db[j * 4 + 1] = cvt_tf32(sb[j].y);
                db[j * 4 + 2] = cvt_tf32(sb[j].z); db[j * 4 + 3] = cvt_tf32(sb[j].w);
            }
            __syncthreads();
            cur = nxt;
        }
    }

#pragma unroll
    for (int mt = 0; mt < 2; mt++) {
        const int r = row0 + wm * 32 + mt * 16 + g;
        int cr0 = r, cr1 = r + 8;
        if (permC) {
            cr0 = (r & 511) * 32 + (r >> 9);
            cr1 = ((r + 8) & 511) * 32 + ((r + 8) >> 9);
        }
#pragma unroll
        for (int nt = 0; nt < 8; nt++) {
            const int c = col0 + wn * 64 + nt * 8 + 2 * tg;
            const float b0 = bias[c], b1 = bias[c + 1];
            *(float2*)&C[(size_t)cr0 * N + c] = make_float2(acc[mt][nt][0] + b0, acc[mt][nt][1] + b1);
            *(float2*)&C[(size_t)cr1 * N + c] = make_float2(acc[mt][nt][2] + b0, acc[mt][nt][3] + b1);
        }
    }
}

// ---------------- attention scores = scale * Q K^T ----------------
__global__ void __launch_bounds__(256) attn_scores(void)
{
    __shared__ float Qs[16][64];
    __shared__ float Ks[16][64];
    const int bh = blockIdx.z, b = bh >> 3, h = bh & 7;
    const int row0 = blockIdx.y * 64, col0 = blockIdx.x * 64;
    const int t = threadIdx.x;
    const int lr = t & 63, lk = (t >> 6) << 2;
    const int tx = t & 15, ty = t >> 4;

    const float* Qp = g_qkv + ((size_t)b * 512 + row0 + lr) * G3 + h * 96 + lk;
    const float* Kp = g_qkv + ((size_t)b * 512 + col0 + lr) * G3 + 768 + h * 96 + lk;

    float acc[4][4];
#pragma unroll
    for (int i = 0; i < 4; i++)
#pragma unroll
        for (int j = 0; j < 4; j++) acc[i][j] = 0.f;

    for (int k0 = 0; k0 < 96; k0 += 16) {
        float4 qv = *(const float4*)(Qp + k0);
        float4 kv = *(const float4*)(Kp + k0);
        __syncthreads();
        Qs[lk + 0][lr] = qv.x; Qs[lk + 1][lr] = qv.y; Qs[lk + 2][lr] = qv.z; Qs[lk + 3][lr] = qv.w;
        Ks[lk + 0][lr] = kv.x; Ks[lk + 1][lr] = kv.y; Ks[lk + 2][lr] = kv.z; Ks[lk + 3][lr] = kv.w;
        __syncthreads();
#pragma unroll
        for (int kk = 0; kk < 16; kk++) {
            float a[4], c[4];
            *(float4*)a = *(const float4*)&Qs[kk][ty << 2];
            *(float4*)c = *(const float4*)&Ks[kk][tx << 2];
#pragma unroll
            for (int i = 0; i < 4; i++)
#pragma unroll
                for (int j = 0; j < 4; j++)
                    acc[i][j] = fmaf(a[i], c[j], acc[i][j]);
        }
    }
    const float scale = 0.1020620726159657f; // 1/sqrt(96)
    float* Cb = g_scores + (size_t)bh * 262144;
#pragma unroll
    for (int i = 0; i < 4; i++)
#pragma unroll
        for (int j = 0; j < 4; j++)
            Cb[(size_t)(row0 + (ty << 2) + i) * 512 + col0 + (tx << 2) + j] = acc[i][j] * scale;
}

// ---------------- softmax over rows of 512 (warp per row) ----------------
__global__ void __launch_bounds__(256) attn_softmax(void)
{
    const int warp = threadIdx.x >> 5, lane = threadIdx.x & 31;
    const size_t row = (size_t)blockIdx.x * 8 + warp;
    float* p = g_scores + row * 512;
    float v[16];
    float m = -1e30f;
#pragma unroll
    for (int i = 0; i < 16; i++) { v[i] = p[lane + (i << 5)]; m = fmaxf(m, v[i]); }
#pragma unroll
    for (int o = 16; o; o >>= 1) m = fmaxf(m, __shfl_xor_sync(0xffffffffu, m, o));
    float s = 0.f;
#pragma unroll
    for (int i = 0; i < 16; i++) { v[i] = expf(v[i] - m); s += v[i]; }
#pragma unroll
    for (int o = 16; o; o >>= 1) s += __shfl_xor_sync(0xffffffffu, s, o);
    const float inv = 1.f / s;
#pragma unroll
    for (int i = 0; i < 16; i++) p[lane + (i << 5)] = v[i] * inv;
}

// ---------------- O = P V ----------------
__global__ void __launch_bounds__(256) attn_av(void)
{
    __shared__ float Ps[32][64];
    __shared__ float Vs[32][96];
    const int bh = blockIdx.y, b = bh >> 3, h = bh & 7;
    const int row0 = blockIdx.x * 64;
    const int t = threadIdx.x;
    const int tx = t & 15, ty = t >> 4;
    const int lr = t & 63, lk = (t >> 6) << 3;
    const int kr = t >> 3, cq = (t & 7) * 12;

    const float* Pp = g_scores + (size_t)bh * 262144 + (size_t)(row0 + lr) * 512 + lk;
    const float* Vp = g_qkv + ((size_t)b * 512 + kr) * G3 + 1536 + h * 96 + cq;

    float acc[4][6];
#pragma unroll
    for (int i = 0; i < 4; i++)
#pragma unroll
        for (int j = 0; j < 6; j++) acc[i][j] = 0.f;

    for (int k0 = 0; k0 < 512; k0 += 32) {
        float4 p0 = *(const float4*)(Pp + k0);
        float4 p1 = *(const float4*)(Pp + k0 + 4);
        const float* vp = Vp + (size_t)k0 * G3;
        float4 v0 = *(const float4*)(vp);
        float4 v1 = *(const float4*)(vp + 4);
        float4 v2 = *(const float4*)(vp + 8);
        __syncthreads();
        Ps[lk + 0][lr] = p0.x; Ps[lk + 1][lr] = p0.y; Ps[lk + 2][lr] = p0.z; Ps[lk + 3][lr] = p0.w;
        Ps[lk + 4][lr] = p1.x; Ps[lk + 5][lr] = p1.y; Ps[lk + 6][lr] = p1.z; Ps[lk + 7][lr] = p1.w;
        *(float4*)&Vs[kr][cq + 0] = v0;
        *(float4*)&Vs[kr][cq + 4] = v1;
        *(float4*)&Vs[kr][cq + 8] = v2;
        __syncthreads();
#pragma unroll
        for (int kk = 0; kk < 32; kk++) {
            float a[4];
            *(float4*)a = *(const float4*)&Ps[kk][ty << 2];
            const float* vr = &Vs[kk][tx * 6];
#pragma unroll
            for (int i = 0; i < 4; i++)
#pragma unroll
                for (int j = 0; j < 6; j++)
                    acc[i][j] = fmaf(a[i], vr[j], acc[i][j]);
        }
    }
#pragma unroll
    for (int i = 0; i < 4; i++) {
        size_t r = (size_t)b * 512 + row0 + (ty << 2) + i;
#pragma unroll
        for (int j = 0; j < 6; j++)
            g_att[r * 768 + h * 96 + tx * 6 + j] = acc[i][j];
    }
}

// ---------------- reset flags + h ping-pong ----------------
__global__ void gru_reset(void)
{
    int i = blockIdx.x * 256 + threadIdx.x;   // grid 384 x 256 = 98304
    if (i < GNB) g_flags[i] = 0;
    g_hping[i] = 0.f;
}

// ---------------- persistent tensor-core GRU layer ----------------
// 96 blocks (48 per dir), 256 threads (8 warps). Block owns 16 units = 48 gate rows
// (3 mma M-tiles). W in smem as swizzled tf32, loaded once. h in [b][u] layout,
// B-fragments loaded directly from L2 (__ldcg). Warps split K (96 each), smem reduce.
#define GRU_WSU  (48 * 768)              // W words
#define GRU_REDW (8 * 48 * 40)           // reduce buffer words (stride 40)
#define GRU_SMEM ((GRU_WSU + GRU_REDW) * 4)

__global__ void __launch_bounds__(256) gru_layer(
    const float* __restrict__ whhF, const float* __restrict__ whhB,
    const float* __restrict__ bhhF, const float* __restrict__ bhhB)
{
    extern __shared__ unsigned smu[];
    unsigned* ws = smu;                       // [48][768] swizzled tf32
    float* red = (float*)(smu + GRU_WSU);     // [8][48*40]
    __shared__ float bsh[48];

    const int tid = threadIdx.x;
    const int warp = tid >> 5, lane = tid & 31;
    const int g = lane >> 2, tg = lane & 3;
    const int blk = blockIdx.x;
    const int dir = blk / 48, ub = blk % 48;
    const int u0 = ub * 16;
    const float* W   = dir ? whhB : whhF;
    const float* bhh = dir ? bhhB : bhhF;

    // load W (rows r = gate*16 + j), swizzled tf32
    for (int r = warp; r < 48; r += 8) {
        const int gr = (r >> 4) * 768 + u0 + (r & 15);
        const unsigned sw = (unsigned)((r & 7) << 2);
        unsigned* dst = ws + r * 768;
        for (int k = lane; k < 768; k += 32)
            dst[k ^ sw] = cvt_tf32(W[(size_t)gr * 768 + k]);
    }
    if (tid < 48) bsh[tid] = bhh[(tid >> 4) * 768 + u0 + (tid & 15)];
    __syncthreads();

    const int kw0 = warp * 96;    // warp's K base

    for (int s = 0; s < 512; s++) {
        if (s > 0) {
            if (tid < 48) {
                while (((volatile int*)g_flags)[dir * 48 + tid] < s) __nanosleep(32);
            }
            __syncthreads();
            __threadfence();
        }
        const float* hsrc = g_hping + (size_t)(((s & 1) * 2 + dir)) * 32 * 768;  // [b][u]

        float acc[3][4][4];
#pragma unroll
        for (int mt = 0; mt < 3; mt++)
#pragma unroll
            for (int nt = 0; nt < 4; nt++)
#pragma unroll
                for (int q = 0; q < 4; q++) acc[mt][nt][q] = 0.f;

#pragma unroll
        for (int pass = 0; pass < 2; pass++) {
            unsigned bf[2][12][2];
#pragma unroll
            for (int np = 0; np < 2; np++) {
                const int bb = (pass * 2 + np) * 8 + g;
                const float* hb = hsrc + (size_t)bb * 768 + kw0;
#pragma unroll
                for (int kt = 0; kt < 12; kt++) {
                    bf[np][kt][0] = __float_as_uint(__ldcg(hb + kt * 8 + tg));
                    bf[np][kt][1] = __float_as_uint(__ldcg(hb + kt * 8 + tg + 4));
                }
            }
#pragma unroll
            for (int kt = 0; kt < 12; kt++) {
                const int kk = kw0 + kt * 8;
                unsigned af[3][4];
#pragma unroll
                for (int mt = 0; mt < 3; mt++) {
                    const int r = mt * 16 + g;
                    const unsigned sw = (unsigned)((r & 7) << 2);
                    const unsigned* wr  = ws + r * 768;
                    const unsigned* wr8 = ws + (r + 8) * 768;
                    af[mt][0] = wr [(kk + tg)     ^ sw];
                    af[mt][1] = wr8[(kk + tg)     ^ sw];
                    af[mt][2] = wr [(kk + tg + 4) ^ sw];
                    af[mt][3] = wr8[(kk + tg + 4) ^ sw];
                }
#pragma unroll
                for (int mt = 0; mt < 3; mt++) {
                    mma_tf32(acc[mt][pass * 2 + 0], af[mt], bf[0][kt]);
                    mma_tf32(acc[mt][pass * 2 + 1], af[mt], bf[1][kt]);
                }
            }
        }

        // store partials to reduce buffer
        {
            float* rp = red + warp * (48 * 40);
#pragma unroll
            for (int mt = 0; mt < 3; mt++)
#pragma unroll
                for (int nt = 0; nt < 4; nt++) {
                    const int r = mt * 16 + g, c = nt * 8 + 2 * tg;
                    *(float2*)&rp[r * 40 + c]       = make_float2(acc[mt][nt][0], acc[mt][nt][1]);
                    *(float2*)&rp[(r + 8) * 40 + c] = make_float2(acc[mt][nt][2], acc[mt][nt][3]);
                }
        }
        __syncthreads();

        // gates: 512 (u,b) pairs, 2 per thread
        const int sx = dir ? (511 - s) : s;
        float* hdst = g_hping + (size_t)((((s & 1) ^ 1) * 2 + dir)) * 32 * 768;
        const float* xwrow = g_xwT + ((size_t)(dir * 512 + sx) * 32) * G3;   // [b][G3]
        float* hq = g_hseqT + ((size_t)(sx * 2 + dir) * 32) * 768;           // [b][u]
        for (int p = tid; p < 512; p += 256) {
            const int ul = p & 15, b = p >> 4;
            float hr = bsh[ul], hz = bsh[16 + ul], hn = bsh[32 + ul];
#pragma unroll
            for (int w = 0; w < 8; w++) {
                const float* q = red + w * (48 * 40);
                hr += q[ul * 40 + b];
                hz += q[(16 + ul) * 40 + b];
                hn += q[(32 + ul) * 40 + b];
            }
            const float* xb = xwrow + (size_t)b * G3;
            const float xr = xb[u0 + ul];
            const float xz = xb[768 + u0 + ul];
            const float xn = xb[1536 + u0 + ul];
            const float rr = 1.f / (1.f + expf(-(xr + hr)));
            const float zz = 1.f / (1.f + expf(-(xz + hz)));
            const float nn = tanhf(xn + rr * hn);
            const float hold = __ldcg(&hsrc[(size_t)b * 768 + u0 + ul]);
            const float hnew = (1.f - zz) * nn + zz * hold;
            hq[(size_t)b * 768 + u0 + ul] = hnew;
            hdst[(size_t)b * 768 + u0 + ul] = __uint_as_float(cvt_tf32(hnew));
        }
        __threadfence();
        __syncthreads();
        if (tid == 0) ((volatile int*)g_flags)[blk] = s + 1;
    }
}

// ---------------- FC: em = h1 @ fc_w^T + fc_b (reads hseqT directly) ----------------
__global__ void __launch_bounds__(256) fc_kernel(
    const float* __restrict__ fcw, const float* __restrict__ fcb)
{
    const int warp = threadIdx.x >> 5, lane = threadIdx.x & 31;
    const int row = blockIdx.x * 8 + warp;
    const int b = row >> 9, sq = row & 511;
    const float* h0p = g_hseqT + ((size_t)(sq * 2 + 0) * 32 + b) * 768;
    const float* h1p = g_hseqT + ((size_t)(sq * 2 + 1) * 32 + b) * 768;
    float s[NC];
#pragma unroll
    for (int c = 0; c < NC; c++) s[c] = 0.f;
    for (int k = lane; k < 768; k += 32) {
        const float hv0 = h0p[k];
        const float hv1 = h1p[k];
#pragma unroll
        for (int c = 0; c < NC; c++) {
            s[c] = fmaf(hv0, __ldg(&fcw[c * 1536 + k]), s[c]);
            s[c] = fmaf(hv1, __ldg(&fcw[c * 1536 + 768 + k]), s[c]);
        }
    }
#pragma unroll
    for (int c = 0; c < NC; c++) {
        float v = s[c];
#pragma unroll
        for (int o = 16; o; o >>= 1) v += __shfl_xor_sync(0xffffffffu, v, o);
        if (lane == 0) g_em[(size_t)row * NC + c] = v + fcb[c];
    }
}

// ---------------- CRF NLL (one warp per batch) ----------------
__global__ void crf_nll_kernel(
    const int* __restrict__ labels, const float* __restrict__ start,
    const float* __restrict__ endw, const float* __restrict__ trans)
{
    int b = blockIdx.x;
    int j = threadIdx.x;
    __shared__ float al[2][NC];
    __shared__ float tr[NC * NC];
    for (int i = j; i < NC * NC; i += 32) tr[i] = trans[i];
    const float* e = g_em + (size_t)b * 512 * NC;
    if (j < NC) al[0][j] = start[j] + e[j];
    __syncwarp();
    for (int t = 1; t < 512; t++) {
        int cur = t & 1, prv = cur ^ 1;
        if (j < NC) {
            float m = -1e30f;
#pragma unroll
            for (int i = 0; i < NC; i++) m = fmaxf(m, al[prv][i] + tr[i * NC + j]);
            float s = 0.f;
#pragma unroll
            for (int i = 0; i < NC; i++) s += expf(al[prv][i] + tr[i * NC + j] - m);
            al[cur][j] = m + logf(s) + e[t * NC + j];
        }
        __syncwarp();
    }
    const int* lab = labels + b * 512;
    float acc = 0.f;
    for (int t = j; t < 512; t += 32) acc += e[t * NC + lab[t]];
    for (int t = j; t < 511; t += 32) acc += tr[lab[t] * NC + lab[t + 1]];
#pragma unroll
    for (int o = 16; o; o >>= 1) acc += __shfl_xor_sync(0xffffffffu, acc, o);
    if (j == 0) {
        float m = -1e30f;
#pragma unroll
        for (int jj = 0; jj < NC; jj++) m = fmaxf(m, al[1][jj] + endw[jj]);
        float s = 0.f;
#pragma unroll
        for (int jj = 0; jj < NC; jj++) s += expf(al[1][jj] + endw[jj] - m);
        float denom = m + logf(s);
        float num = acc + start[lab[0]] + endw[lab[511]];
        g_nll[b] = denom - num;
    }
}

__global__ void finalize_loss(float* out)
{
    float s = 0.f;
    for (int i = 0; i < 32; i++) s += g_nll[i];
    out[0] = s;
}

// ---------------- Viterbi (one warp per batch) ----------------
__global__ void viterbi_kernel(
    const float* __restrict__ start, const float* __restrict__ endw,
    const float* __restrict__ trans, float* __restrict__ out)
{
    int b = blockIdx.x;
    int j = threadIdx.x;
    __shared__ float al[2][NC];
    __shared__ float tr[NC * NC];
    __shared__ unsigned char bp[511][NC];
    for (int i = j; i < NC * NC; i += 32) tr[i] = trans[i];
    const float* e = g_em + (size_t)b * 512 * NC;
    if (j < NC) al[0][j] = start[j] + e[j];
    __syncwarp();
    for (int t = 1; t < 512; t++) {
        int cur = t & 1, prv = cur ^ 1;
        if (j < NC) {
            float best = -1e30f;
            int arg = 0;
#pragma unroll
            for (int i = 0; i < NC; i++) {
                float sc = al[prv][i] + tr[i * NC + j];
                if (sc > best) { best = sc; arg = i; }
            }
            al[cur][j] = best + e[t * NC + j];
            bp[t - 1][j] = (unsigned char)arg;
        }
        __syncwarp();
    }
    if (j == 0) {
        float best = -1e30f;
        int last = 0;
#pragma unroll
        for (int jj = 0; jj < NC; jj++) {
            float sc = al[1][jj] + endw[jj];
            if (sc > best) { best = sc; last = jj; }
        }
        float* po = out + 1 + (size_t)b * 512;
        po[511] = (float)last;
        int tag = last;
        for (int t = 510; t >= 0; t--) {
            tag = bp[t][tag];
            po[t] = (float)tag;
        }
    }
}

// ---------------- launch ----------------
extern "C" void kernel_launch(void* const* d_in, const int* in_sizes, int n_in,
                              void* d_out, int out_size)
{
    const float* emb   = (const float*)d_in[0];
    const float* ipw   = (const float*)d_in[1];
    const float* ipb   = (const float*)d_in[2];
    const float* opw   = (const float*)d_in[3];
    const float* opb   = (const float*)d_in[4];
    const float* fcw   = (const float*)d_in[5];
    const float* fcb   = (const float*)d_in[6];
    const float* cstart= (const float*)d_in[7];
    const float* cend  = (const float*)d_in[8];
    const float* ctr   = (const float*)d_in[9];
    const int*   lab   = (const int*)d_in[10];
    const float* wih0f = (const float*)d_in[11];
    const float* whh0f = (const float*)d_in[12];
    const float* bih0f = (const float*)d_in[13];
    const float* bhh0f = (const float*)d_in[14];
    const float* wih0b = (const float*)d_in[15];
    const float* whh0b = (const float*)d_in[16];
    const float* bih0b = (const float*)d_in[17];
    const float* bhh0b = (const float*)d_in[18];
    const float* wih1f = (const float*)d_in[19];
    const float* whh1f = (const float*)d_in[20];
    const float* bih1f = (const float*)d_in[21];
    const float* bhh1f = (const float*)d_in[22];
    const float* wih1b = (const float*)d_in[23];
    const float* whh1b = (const float*)d_in[24];
    const float* bih1b = (const float*)d_in[25];
    const float* bhh1b = (const float*)d_in[26];
    float* out = (float*)d_out;

    static int attr_set = 0;
    if (!attr_set) {
        cudaFuncSetAttribute(gru_layer, cudaFuncAttributeMaxDynamicSharedMemorySize, GRU_SMEM);
        cudaFuncSetAttribute(tgemm128, cudaFuncAttributeMaxDynamicSharedMemorySize, TG_SMEM);
        attr_set = 1;
    }

    void* p;
    cudaGetSymbolAddress(&p, g_qkv);   float* qkv  = (float*)p;
    cudaGetSymbolAddress(&p, g_att);   float* att  = (float*)p;
    cudaGetSymbolAddress(&p, g_x);     float* x    = (float*)p;
    cudaGetSymbolAddress(&p, g_xwT);   float* xwT  = (float*)p;
    cudaGetSymbolAddress(&p, g_hseqT); float* hsq  = (float*)p;

    const size_t DIRSTRIDE = (size_t)512 * 32 * G3;

    // 1. QKV projection
    tgemm128<<<dim3(G3 / 128, MTOT / 128), 256, TG_SMEM>>>(emb, ipw, ipb, qkv, MTOT, G3, 768, 0, 0);
    // 2. attention
    attn_scores<<<dim3(8, 8, 256), 256>>>();
    attn_softmax<<<16384, 256>>>();
    attn_av<<<dim3(8, 256), 256>>>();
    // 3. out projection
    tgemm128<<<dim3(768 / 128, MTOT / 128), 256, TG_SMEM>>>(att, opw, opb, x, MTOT, 768, 768, 0, 0);

    // 4. GRU layers
    for (int l = 0; l < 2; l++) {
        const float* xin  = l ? hsq : x;
        int gather        = l ? 1 : 0;
        int K             = l ? 1536 : 768;
        const float* wihF = l ? wih1f : wih0f;
        const float* wihB = l ? wih1b : wih0b;
        const float* bihF = l ? bih1f : bih0f;
        const float* bihB = l ? bih1b : bih0b;
        const float* whhF = l ? whh1f : whh0f;
        const float* whhB = l ? whh1b : whh0b;
        const float* bhhF = l ? bhh1f : bhh0f;
        const float* bhhB = l ? bhh1b : bhh0b;

        tgemm128<<<dim3(G3 / 128, MTOT / 128), 256, TG_SMEM>>>(xin, wihF, bihF, xwT, MTOT, G3, K, gather, 1);
        tgemm128<<<dim3(G3 / 128, MTOT / 128), 256, TG_SMEM>>>(xin, wihB, bihB, xwT + DIRSTRIDE, MTOT, G3, K, gather, 1);
        gru_reset<<<384, 256>>>();
        gru_layer<<<GNB, 256, GRU_SMEM>>>(whhF, whhB, bhhF, bhhB);
    }

    // 5. FC + CRF + Viterbi
    fc_kernel<<<MTOT / 8, 256>>>(fcw, fcb);
    crf_nll_kernel<<<32, 32>>>(lab, cstart, cend, ctr);
    finalize_loss<<<1, 1>>>(out);
    viterbi_kernel<<<32, 32>>>(cstart, cend, ctr, out);
}

// round 8
// speedup vs baseline: 2.3775x; 1.0406x over previous
#include <cuda_runtime.h>
#include <math.h>

#define MTOT 16384   // B*S
#define G3   2304    // 3*H
#define HID  768
#define NC   9
#define GNB  96      // persistent GRU blocks (48 per dir)

// ---------------- device scratch ----------------
__device__ float g_qkv[(size_t)MTOT * G3];
__device__ float g_scores[(size_t)256 * 512 * 512];
__device__ float g_att[(size_t)MTOT * 768];
__device__ float g_x[(size_t)MTOT * 768];
__device__ float g_xwT[(size_t)2 * 512 * 32 * G3];     // [dir][s][b][G3]
__device__ float g_hseqT[(size_t)512 * 2 * 32 * 768];  // [s][dir][b][u]
__device__ float g_hping[2 * 2 * 32 * HID];            // [parity][dir][b][u]
__device__ int   g_flags[GNB];
__device__ float g_em[(size_t)MTOT * NC];
__device__ float g_nll[32];

// ---------------- tf32 helpers ----------------
__device__ __forceinline__ unsigned cvt_tf32(float v) {
    unsigned r;
    asm("cvt.rna.tf32.f32 %0, %1;" : "=r"(r) : "f"(v));
    return r;
}
__device__ __forceinline__ void mma_tf32(float* c, const unsigned* a, const unsigned* b) {
    asm volatile(
        "mma.sync.aligned.m16n8k8.row.col.f32.tf32.tf32.f32 "
        "{%0,%1,%2,%3}, {%4,%5,%6,%7}, {%8,%9}, {%0,%1,%2,%3};"
        : "+f"(c[0]), "+f"(c[1]), "+f"(c[2]), "+f"(c[3])
        : "r"(a[0]), "r"(a[1]), "r"(a[2]), "r"(a[3]), "r"(b[0]), "r"(b[1]));
}

// ---------------- fast gate nonlinearities (1 MUFU each) ----------------
__device__ __forceinline__ float ftanh(float x) {
    float t;
    asm("tanh.approx.f32 %0, %1;" : "=f"(t) : "f"(x));
    return t;
}
__device__ __forceinline__ float fsig(float x) {
    float t;
    asm("tanh.approx.f32 %0, %1;" : "=f"(t) : "f"(x * 0.5f));
    return fmaf(0.5f, t, 0.5f);
}

// ---------------- tf32 tensor-core NT GEMM ----------------
// C[M,N] = A[M,K] @ B[N,K]^T + bias ; M%128==0, N%128==0, K%32==0
// gatherA: A row r=(b*512+s), element k -> g_hseqT layout [s][dir][b][u]
// permC:   C row r=(b*512+s) stored at row' = s*32+b (into xwT [s][b][N])
#define TG_BUF 4608               // 128*36
#define TG_SMEM (4 * TG_BUF * 4)

__global__ void __launch_bounds__(256) tgemm128(
    const float* __restrict__ A, const float* __restrict__ B,
    const float* __restrict__ bias, float* __restrict__ C,
    int M, int N, int K, int gatherA, int permC)
{
    extern __shared__ unsigned smu[];
    unsigned* As = smu;               // [2][128][36]
    unsigned* Bs = smu + 2 * TG_BUF;  // [2][128][36]

    const int t = threadIdx.x;
    const int lane = t & 31;
    const int wid = t >> 5;
    const int wm = wid & 3;
    const int wn = wid >> 2;
    const int g  = lane >> 2;
    const int tg = lane & 3;

    const int row0 = blockIdx.y * 128;
    const int col0 = blockIdx.x * 128;

    const int grow = t >> 1;
    const int gk   = (t & 1) * 16;
    const int rowA = row0 + grow;

    size_t gb0 = 0, gb1 = 0;
    const float* Ap = A + (size_t)rowA * K + gk;
    if (gatherA) {
        int bb = rowA >> 9, sq = rowA & 511;
        gb0 = ((size_t)(sq * 2) * 32 + bb) * 768;
        gb1 = ((size_t)(sq * 2 + 1) * 32 + bb) * 768;
    }
    const float* Bp = B + (size_t)(col0 + grow) * K + gk;

    float acc[2][8][4];
#pragma unroll
    for (int mt = 0; mt < 2; mt++)
#pragma unroll
        for (int nt = 0; nt < 8; nt++)
#pragma unroll
            for (int q = 0; q < 4; q++) acc[mt][nt][q] = 0.f;

    // prologue chunk 0
    {
        const float* ApC = gatherA ? (A + (gk < 768 ? gb0 + gk : gb1 + gk - 768)) : Ap;
#pragma unroll
        for (int j = 0; j < 4; j++) {
            float4 va = *(const float4*)(ApC + j * 4);
            float4 vb = *(const float4*)(Bp + j * 4);
            unsigned* da = &As[grow * 36 + gk + j * 4];
            unsigned* db = &Bs[grow * 36 + gk + j * 4];
            da[0] = cvt_tf32(va.x); da[1] = cvt_tf32(va.y);
            da[2] = cvt_tf32(va.z); da[3] = cvt_tf32(va.w);
            db[0] = cvt_tf32(vb.x); db[1] = cvt_tf32(vb.y);
            db[2] = cvt_tf32(vb.z); db[3] = cvt_tf32(vb.w);
        }
    }
    __syncthreads();

    int cur = 0;
    for (int kt = 0; kt < K; kt += 32) {
        const bool more = (kt + 32) < K;
        float4 sa[4], sb[4];
        if (more) {
            const int o = kt + 32 + gk;
            const float* ApC = gatherA ? (A + (o < 768 ? gb0 + o : gb1 + o - 768)) : (Ap + kt + 32);
#pragma unroll
            for (int j = 0; j < 4; j++) {
                sa[j] = *(const float4*)(ApC + j * 4);
                sb[j] = *(const float4*)(Bp + kt + 32 + j * 4);
            }
        }
        const unsigned* Ab = As + cur * TG_BUF;
        const unsigned* Bb = Bs + cur * TG_BUF;
#pragma unroll
        for (int ks = 0; ks < 4; ks++) {
            const int kk = ks * 8;
            unsigned af[2][4];
#pragma unroll
            for (int mt = 0; mt < 2; mt++) {
                const int r = wm * 32 + mt * 16 + g;
                af[mt][0] = Ab[(r)     * 36 + kk + tg];
                af[mt][1] = Ab[(r + 8) * 36 + kk + tg];
                af[mt][2] = Ab[(r)     * 36 + kk + tg + 4];
                af[mt][3] = Ab[(r + 8) * 36 + kk + tg + 4];
            }
            unsigned bf[8][2];
#pragma unroll
            for (int nt = 0; nt < 8; nt++) {
                const int n = wn * 64 + nt * 8 + g;
                bf[nt][0] = Bb[n * 36 + kk + tg];
                bf[nt][1] = Bb[n * 36 + kk + tg + 4];
            }
#pragma unroll
            for (int mt = 0; mt < 2; mt++)
#pragma unroll
                for (int nt = 0; nt < 8; nt++)
                    mma_tf32(acc[mt][nt], af[mt], bf[nt]);
        }
        if (more) {
            const int nxt = cur ^ 1;
            unsigned* da = &As[nxt * TG_BUF + grow * 36 + gk];
            unsigned* db = &Bs[nxt * TG_BUF + grow * 36 + gk];
#pragma unroll
            for (int j = 0; j < 4; j++) {
                da[j * 4 + 0] = cvt_tf32(sa[j].x); da[j * 4 + 1] = cvt_tf32(sa[j].y);
                da[j * 4 + 2] = cvt_tf32(sa[j].z); da[j * 4 + 3] = cvt_tf32(sa[j].w);
                db[j * 4 + 0] = cvt_tf32(sb[j].x); db[j * 4 + 1] = cvt_tf32(sb[j].y);
                db[j * 4 + 2] = cvt_tf32(sb[j].z); db[j * 4 + 3] = cvt_tf32(sb[j].w);
            }
            __syncthreads();
            cur = nxt;
        }
    }

#pragma unroll
    for (int mt = 0; mt < 2; mt++) {
        const int r = row0 + wm * 32 + mt * 16 + g;
        int cr0 = r, cr1 = r + 8;
        if (permC) {
            cr0 = (r & 511) * 32 + (r >> 9);
            cr1 = ((r + 8) & 511) * 32 + ((r + 8) >> 9);
        }
#pragma unroll
        for (int nt = 0; nt < 8; nt++) {
            const int c = col0 + wn * 64 + nt * 8 + 2 * tg;
            const float b0 = bias[c], b1 = bias[c + 1];
            *(float2*)&C[(size_t)cr0 * N + c] = make_float2(acc[mt][nt][0] + b0, acc[mt][nt][1] + b1);
            *(float2*)&C[(size_t)cr1 * N + c] = make_float2(acc[mt][nt][2] + b0, acc[mt][nt][3] + b1);
        }
    }
}

// ---------------- attention scores = scale * Q K^T ----------------
__global__ void __launch_bounds__(256) attn_scores(void)
{
    __shared__ float Qs[16][64];
    __shared__ float Ks[16][64];
    const int bh = blockIdx.z, b = bh >> 3, h = bh & 7;
    const int row0 = blockIdx.y * 64, col0 = blockIdx.x * 64;
    const int t = threadIdx.x;
    const int lr = t & 63, lk = (t >> 6) << 2;
    const int tx = t & 15, ty = t >> 4;

    const float* Qp = g_qkv + ((size_t)b * 512 + row0 + lr) * G3 + h * 96 + lk;
    const float* Kp = g_qkv + ((size_t)b * 512 + col0 + lr) * G3 + 768 + h * 96 + lk;

    float acc[4][4];
#pragma unroll
    for (int i = 0; i < 4; i++)
#pragma unroll
        for (int j = 0; j < 4; j++) acc[i][j] = 0.f;

    for (int k0 = 0; k0 < 96; k0 += 16) {
        float4 qv = *(const float4*)(Qp + k0);
        float4 kv = *(const float4*)(Kp + k0);
        __syncthreads();
        Qs[lk + 0][lr] = qv.x; Qs[lk + 1][lr] = qv.y; Qs[lk + 2][lr] = qv.z; Qs[lk + 3][lr] = qv.w;
        Ks[lk + 0][lr] = kv.x; Ks[lk + 1][lr] = kv.y; Ks[lk + 2][lr] = kv.z; Ks[lk + 3][lr] = kv.w;
        __syncthreads();
#pragma unroll
        for (int kk = 0; kk < 16; kk++) {
            float a[4], c[4];
            *(float4*)a = *(const float4*)&Qs[kk][ty << 2];
            *(float4*)c = *(const float4*)&Ks[kk][tx << 2];
#pragma unroll
            for (int i = 0; i < 4; i++)
#pragma unroll
                for (int j = 0; j < 4; j++)
                    acc[i][j] = fmaf(a[i], c[j], acc[i][j]);
        }
    }
    const float scale = 0.1020620726159657f; // 1/sqrt(96)
    float* Cb = g_scores + (size_t)bh * 262144;
#pragma unroll
    for (int i = 0; i < 4; i++)
#pragma unroll
        for (int j = 0; j < 4; j++)
            Cb[(size_t)(row0 + (ty << 2) + i) * 512 + col0 + (tx << 2) + j] = acc[i][j] * scale;
}

// ---------------- softmax over rows of 512 (warp per row) ----------------
__global__ void __launch_bounds__(256) attn_softmax(void)
{
    const int warp = threadIdx.x >> 5, lane = threadIdx.x & 31;
    const size_t row = (size_t)blockIdx.x * 8 + warp;
    float* p = g_scores + row * 512;
    float v[16];
    float m = -1e30f;
#pragma unroll
    for (int i = 0; i < 16; i++) { v[i] = p[lane + (i << 5)]; m = fmaxf(m, v[i]); }
#pragma unroll
    for (int o = 16; o; o >>= 1) m = fmaxf(m, __shfl_xor_sync(0xffffffffu, m, o));
    float s = 0.f;
#pragma unroll
    for (int i = 0; i < 16; i++) { v[i] = expf(v[i] - m); s += v[i]; }
#pragma unroll
    for (int o = 16; o; o >>= 1) s += __shfl_xor_sync(0xffffffffu, s, o);
    const float inv = 1.f / s;
#pragma unroll
    for (int i = 0; i < 16; i++) p[lane + (i << 5)] = v[i] * inv;
}

// ---------------- O = P V ----------------
__global__ void __launch_bounds__(256) attn_av(void)
{
    __shared__ float Ps[32][64];
    __shared__ float Vs[32][96];
    const int bh = blockIdx.y, b = bh >> 3, h = bh & 7;
    const int row0 = blockIdx.x * 64;
    const int t = threadIdx.x;
    const int tx = t & 15, ty = t >> 4;
    const int lr = t & 63, lk = (t >> 6) << 3;
    const int kr = t >> 3, cq = (t & 7) * 12;

    const float* Pp = g_scores + (size_t)bh * 262144 + (size_t)(row0 + lr) * 512 + lk;
    const float* Vp = g_qkv + ((size_t)b * 512 + kr) * G3 + 1536 + h * 96 + cq;

    float acc[4][6];
#pragma unroll
    for (int i = 0; i < 4; i++)
#pragma unroll
        for (int j = 0; j < 6; j++) acc[i][j] = 0.f;

    for (int k0 = 0; k0 < 512; k0 += 32) {
        float4 p0 = *(const float4*)(Pp + k0);
        float4 p1 = *(const float4*)(Pp + k0 + 4);
        const float* vp = Vp + (size_t)k0 * G3;
        float4 v0 = *(const float4*)(vp);
        float4 v1 = *(const float4*)(vp + 4);
        float4 v2 = *(const float4*)(vp + 8);
        __syncthreads();
        Ps[lk + 0][lr] = p0.x; Ps[lk + 1][lr] = p0.y; Ps[lk + 2][lr] = p0.z; Ps[lk + 3][lr] = p0.w;
        Ps[lk + 4][lr] = p1.x; Ps[lk + 5][lr] = p1.y; Ps[lk + 6][lr] = p1.z; Ps[lk + 7][lr] = p1.w;
        *(float4*)&Vs[kr][cq + 0] = v0;
        *(float4*)&Vs[kr][cq + 4] = v1;
        *(float4*)&Vs[kr][cq + 8] = v2;
        __syncthreads();
#pragma unroll
        for (int kk = 0; kk < 32; kk++) {
            float a[4];
            *(float4*)a = *(const float4*)&Ps[kk][ty << 2];
            const float* vr = &Vs[kk][tx * 6];
#pragma unroll
            for (int i = 0; i < 4; i++)
#pragma unroll
                for (int j = 0; j < 6; j++)
                    acc[i][j] = fmaf(a[i], vr[j], acc[i][j]);
        }
    }
#pragma unroll
    for (int i = 0; i < 4; i++) {
        size_t r = (size_t)b * 512 + row0 + (ty << 2) + i;
#pragma unroll
        for (int j = 0; j < 6; j++)
            g_att[r * 768 + h * 96 + tx * 6 + j] = acc[i][j];
    }
}

// ---------------- reset flags + h ping-pong ----------------
__global__ void gru_reset(void)
{
    int i = blockIdx.x * 256 + threadIdx.x;   // grid 384 x 256 = 98304
    if (i < GNB) g_flags[i] = 0;
    g_hping[i] = 0.f;
}

// ---------------- persistent tensor-core GRU layer ----------------
// 96 blocks (48 per dir), 256 threads (8 warps). Block owns 16 units = 48 gate rows
// (3 mma M-tiles). W in smem as swizzled tf32, loaded once. h in [b][u] layout,
// B-fragments loaded directly from L2 (__ldcg). Warps split K (96 each), smem reduce.
// Cross-block sync: per-segment flags, st.release.gpu / ld.acquire.gpu (no full fences).
#define GRU_WSU  (48 * 768)              // W words
#define GRU_REDW (8 * 48 * 40)           // reduce buffer words (stride 40)
#define GRU_SMEM ((GRU_WSU + GRU_REDW) * 4)

__global__ void __launch_bounds__(256) gru_layer(
    const float* __restrict__ whhF, const float* __restrict__ whhB,
    const float* __restrict__ bhhF, const float* __restrict__ bhhB)
{
    extern __shared__ unsigned smu[];
    unsigned* ws = smu;                       // [48][768] swizzled tf32
    float* red = (float*)(smu + GRU_WSU);     // [8][48*40]
    __shared__ float bsh[48];

    const int tid = threadIdx.x;
    const int warp = tid >> 5, lane = tid & 31;
    const int g = lane >> 2, tg = lane & 3;
    const int blk = blockIdx.x;
    const int dir = blk / 48, ub = blk % 48;
    const int u0 = ub * 16;
    const float* W   = dir ? whhB : whhF;
    const float* bhh = dir ? bhhB : bhhF;

    // load W (rows r = gate*16 + j), swizzled tf32
    for (int r = warp; r < 48; r += 8) {
        const int gr = (r >> 4) * 768 + u0 + (r & 15);
        const unsigned sw = (unsigned)((r & 7) << 2);
        unsigned* dst = ws + r * 768;
        for (int k = lane; k < 768; k += 32)
            dst[k ^ sw] = cvt_tf32(W[(size_t)gr * 768 + k]);
    }
    if (tid < 48) bsh[tid] = bhh[(tid >> 4) * 768 + u0 + (tid & 15)];
    __syncthreads();

    const int kw0 = warp * 96;    // warp's K base
    const int ul = tid & 15;      // gates: unit-local
    const int b0 = tid >> 4;      // gates: batch pair 0 (0..15)
    const int b1 = b0 + 16;       // gates: batch pair 1 (16..31)

    for (int s = 0; s < 512; s++) {
        const int sx = dir ? (511 - s) : s;
        const float* xwrow = g_xwT + ((size_t)(dir * 512 + sx) * 32) * G3;   // [b][G3]

        // prefetch gate inputs (independent of h) BEFORE the flag wait
        const float* xp0 = xwrow + (size_t)b0 * G3 + u0 + ul;
        const float* xp1 = xwrow + (size_t)b1 * G3 + u0 + ul;
        const float xr0 = __ldcg(xp0), xz0 = __ldcg(xp0 + 768), xn0 = __ldcg(xp0 + 1536);
        const float xr1 = __ldcg(xp1), xz1 = __ldcg(xp1 + 768), xn1 = __ldcg(xp1 + 1536);

        if (s > 0) {
            if (tid < 48) {
                const int* fp = g_flags + dir * 48 + tid;
                int v;
                for (;;) {
                    asm volatile("ld.acquire.gpu.global.b32 %0, [%1];" : "=r"(v) : "l"(fp) : "memory");
                    if (v >= s) break;
                    __nanosleep(20);
                }
            }
            __syncthreads();
        }
        const float* hsrc = g_hping + (size_t)(((s & 1) * 2 + dir)) * 32 * 768;  // [b][u]

        // prefetch old h for the gate update
        const float hold0 = __ldcg(&hsrc[(size_t)b0 * 768 + u0 + ul]);
        const float hold1 = __ldcg(&hsrc[(size_t)b1 * 768 + u0 + ul]);

        float acc[3][4][4];
#pragma unroll
        for (int mt = 0; mt < 3; mt++)
#pragma unroll
            for (int nt = 0; nt < 4; nt++)
#pragma unroll
                for (int q = 0; q < 4; q++) acc[mt][nt][q] = 0.f;

#pragma unroll
        for (int pass = 0; pass < 2; pass++) {
            unsigned bf[2][12][2];
#pragma unroll
            for (int np = 0; np < 2; np++) {
                const int bb = (pass * 2 + np) * 8 + g;
                const float* hb = hsrc + (size_t)bb * 768 + kw0;
#pragma unroll
                for (int kt = 0; kt < 12; kt++) {
                    bf[np][kt][0] = __float_as_uint(__ldcg(hb + kt * 8 + tg));
                    bf[np][kt][1] = __float_as_uint(__ldcg(hb + kt * 8 + tg + 4));
                }
            }
#pragma unroll
            for (int kt = 0; kt < 12; kt++) {
                const int kk = kw0 + kt * 8;
                unsigned af[3][4];
#pragma unroll
                for (int mt = 0; mt < 3; mt++) {
                    const int r = mt * 16 + g;
                    const unsigned sw = (unsigned)((r & 7) << 2);
                    const unsigned* wr  = ws + r * 768;
                    const unsigned* wr8 = ws + (r + 8) * 768;
                    af[mt][0] = wr [(kk + tg)     ^ sw];
                    af[mt][1] = wr8[(kk + tg)     ^ sw];
                    af[mt][2] = wr [(kk + tg + 4) ^ sw];
                    af[mt][3] = wr8[(kk + tg + 4) ^ sw];
                }
#pragma unroll
                for (int mt = 0; mt < 3; mt++) {
                    mma_tf32(acc[mt][pass * 2 + 0], af[mt], bf[0][kt]);
                    mma_tf32(acc[mt][pass * 2 + 1], af[mt], bf[1][kt]);
                }
            }
        }

        // store partials to reduce buffer
        {
            float* rp = red + warp * (48 * 40);
#pragma unroll
            for (int mt = 0; mt < 3; mt++)
#pragma unroll
                for (int nt = 0; nt < 4; nt++) {
                    const int r = mt * 16 + g, c = nt * 8 + 2 * tg;
                    *(float2*)&rp[r * 40 + c]       = make_float2(acc[mt][nt][0], acc[mt][nt][1]);
                    *(float2*)&rp[(r + 8) * 40 + c] = make_float2(acc[mt][nt][2], acc[mt][nt][3]);
                }
        }
        __syncthreads();

        // gates (2 pairs per thread, fast tanh-based nonlinearities)
        float* hdst = g_hping + (size_t)((((s & 1) ^ 1) * 2 + dir)) * 32 * 768;
        float* hq = g_hseqT + ((size_t)(sx * 2 + dir) * 32) * 768;           // [b][u]
        {
            float hr0 = bsh[ul], hz0 = bsh[16 + ul], hn0 = bsh[32 + ul];
            float hr1 = hr0, hz1 = hz0, hn1 = hn0;
#pragma unroll
            for (int w = 0; w < 8; w++) {
                const float* q = red + w * (48 * 40);
                hr0 += q[ul * 40 + b0];        hr1 += q[ul * 40 + b1];
                hz0 += q[(16 + ul) * 40 + b0]; hz1 += q[(16 + ul) * 40 + b1];
                hn0 += q[(32 + ul) * 40 + b0]; hn1 += q[(32 + ul) * 40 + b1];
            }
            const float rr0 = fsig(xr0 + hr0);
            const float zz0 = fsig(xz0 + hz0);
            const float nn0 = ftanh(fmaf(rr0, hn0, xn0));
            const float hnew0 = fmaf(zz0, hold0 - nn0, nn0);
            const float rr1 = fsig(xr1 + hr1);
            const float zz1 = fsig(xz1 + hz1);
            const float nn1 = ftanh(fmaf(rr1, hn1, xn1));
            const float hnew1 = fmaf(zz1, hold1 - nn1, nn1);
            hq[(size_t)b0 * 768 + u0 + ul] = hnew0;
            hq[(size_t)b1 * 768 + u0 + ul] = hnew1;
            hdst[(size_t)b0 * 768 + u0 + ul] = __uint_as_float(cvt_tf32(hnew0));
            hdst[(size_t)b1 * 768 + u0 + ul] = __uint_as_float(cvt_tf32(hnew1));
        }
        __syncthreads();
        if (tid == 0) {
            asm volatile("st.release.gpu.global.b32 [%0], %1;"
                         :: "l"(g_flags + blk), "r"(s + 1) : "memory");
        }
    }
}

// ---------------- FC: em = h1 @ fc_w^T + fc_b (reads hseqT directly) ----------------
__global__ void __launch_bounds__(256) fc_kernel(
    const float* __restrict__ fcw, const float* __restrict__ fcb)
{
    const int warp = threadIdx.x >> 5, lane = threadIdx.x & 31;
    const int row = blockIdx.x * 8 + warp;
    const int b = row >> 9, sq = row & 511;
    const float* h0p = g_hseqT + ((size_t)(sq * 2 + 0) * 32 + b) * 768;
    const float* h1p = g_hseqT + ((size_t)(sq * 2 + 1) * 32 + b) * 768;
    float s[NC];
#pragma unroll
    for (int c = 0; c < NC; c++) s[c] = 0.f;
    for (int k = lane; k < 768; k += 32) {
        const float hv0 = h0p[k];
        const float hv1 = h1p[k];
#pragma unroll
        for (int c = 0; c < NC; c++) {
            s[c] = fmaf(hv0, __ldg(&fcw[c * 1536 + k]), s[c]);
            s[c] = fmaf(hv1, __ldg(&fcw[c * 1536 + 768 + k]), s[c]);
        }
    }
#pragma unroll
    for (int c = 0; c < NC; c++) {
        float v = s[c];
#pragma unroll
        for (int o = 16; o; o >>= 1) v += __shfl_xor_sync(0xffffffffu, v, o);
        if (lane == 0) g_em[(size_t)row * NC + c] = v + fcb[c];
    }
}

// ---------------- CRF NLL (one warp per batch) ----------------
__global__ void crf_nll_kernel(
    const int* __restrict__ labels, const float* __restrict__ start,
    const float* __restrict__ endw, const float* __restrict__ trans)
{
    int b = blockIdx.x;
    int j = threadIdx.x;
    __shared__ float al[2][NC];
    __shared__ float tr[NC * NC];
    for (int i = j; i < NC * NC; i += 32) tr[i] = trans[i];
    const float* e = g_em + (size_t)b * 512 * NC;
    if (j < NC) al[0][j] = start[j] + e[j];
    __syncwarp();
    for (int t = 1; t < 512; t++) {
        int cur = t & 1, prv = cur ^ 1;
        if (j < NC) {
            float m = -1e30f;
#pragma unroll
            for (int i = 0; i < NC; i++) m = fmaxf(m, al[prv][i] + tr[i * NC + j]);
            float s = 0.f;
#pragma unroll
            for (int i = 0; i < NC; i++) s += expf(al[prv][i] + tr[i * NC + j] - m);
            al[cur][j] = m + logf(s) + e[t * NC + j];
        }
        __syncwarp();
    }
    const int* lab = labels + b * 512;
    float acc = 0.f;
    for (int t = j; t < 512; t += 32) acc += e[t * NC + lab[t]];
    for (int t = j; t < 511; t += 32) acc += tr[lab[t] * NC + lab[t + 1]];
#pragma unroll
    for (int o = 16; o; o >>= 1) acc += __shfl_xor_sync(0xffffffffu, acc, o);
    if (j == 0) {
        float m = -1e30f;
#pragma unroll
        for (int jj = 0; jj < NC; jj++) m = fmaxf(m, al[1][jj] + endw[jj]);
        float s = 0.f;
#pragma unroll
        for (int jj = 0; jj < NC; jj++) s += expf(al[1][jj] + endw[jj] - m);
        float denom = m + logf(s);
        float num = acc + start[lab[0]] + endw[lab[511]];
        g_nll[b] = denom - num;
    }
}

__global__ void finalize_loss(float* out)
{
    float s = 0.f;
    for (int i = 0; i < 32; i++) s += g_nll[i];
    out[0] = s;
}

// ---------------- Viterbi (one warp per batch) ----------------
__global__ void viterbi_kernel(
    const float* __restrict__ start, const float* __restrict__ endw,
    const float* __restrict__ trans, float* __restrict__ out)
{
    int b = blockIdx.x;
    int j = threadIdx.x;
    __shared__ float al[2][NC];
    __shared__ float tr[NC * NC];
    __shared__ unsigned char bp[511][NC];
    for (int i = j; i < NC * NC; i += 32) tr[i] = trans[i];
    const float* e = g_em + (size_t)b * 512 * NC;
    if (j < NC) al[0][j] = start[j] + e[j];
    __syncwarp();
    for (int t = 1; t < 512; t++) {
        int cur = t & 1, prv = cur ^ 1;
        if (j < NC) {
            float best = -1e30f;
            int arg = 0;
#pragma unroll
            for (int i = 0; i < NC; i++) {
                float sc = al[prv][i] + tr[i * NC + j];
                if (sc > best) { best = sc; arg = i; }
            }
            al[cur][j] = best + e[t * NC + j];
            bp[t - 1][j] = (unsigned char)arg;
        }
        __syncwarp();
    }
    if (j == 0) {
        float best = -1e30f;
        int last = 0;
#pragma unroll
        for (int jj = 0; jj < NC; jj++) {
            float sc = al[1][jj] + endw[jj];
            if (sc > best) { best = sc; last = jj; }
        }
        float* po = out + 1 + (size_t)b * 512;
        po[511] = (float)last;
        int tag = last;
        for (int t = 510; t >= 0; t--) {
            tag = bp[t][tag];
            po[t] = (float)tag;
        }
    }
}

// ---------------- launch ----------------
extern "C" void kernel_launch(void* const* d_in, const int* in_sizes, int n_in,
                              void* d_out, int out_size)
{
    const float* emb   = (const float*)d_in[0];
    const float* ipw   = (const float*)d_in[1];
    const float* ipb   = (const float*)d_in[2];
    const float* opw   = (const float*)d_in[3];
    const float* opb   = (const float*)d_in[4];
    const float* fcw   = (const float*)d_in[5];
    const float* fcb   = (const float*)d_in[6];
    const float* cstart= (const float*)d_in[7];
    const float* cend  = (const float*)d_in[8];
    const float* ctr   = (const float*)d_in[9];
    const int*   lab   = (const int*)d_in[10];
    const float* wih0f = (const float*)d_in[11];
    const float* whh0f = (const float*)d_in[12];
    const float* bih0f = (const float*)d_in[13];
    const float* bhh0f = (const float*)d_in[14];
    const float* wih0b = (const float*)d_in[15];
    const float* whh0b = (const float*)d_in[16];
    const float* bih0b = (const float*)d_in[17];
    const float* bhh0b = (const float*)d_in[18];
    const float* wih1f = (const float*)d_in[19];
    const float* whh1f = (const float*)d_in[20];
    const float* bih1f = (const float*)d_in[21];
    const float* bhh1f = (const float*)d_in[22];
    const float* wih1b = (const float*)d_in[23];
    const float* whh1b = (const float*)d_in[24];
    const float* bih1b = (const float*)d_in[25];
    const float* bhh1b = (const float*)d_in[26];
    float* out = (float*)d_out;

    static int attr_set = 0;
    if (!attr_set) {
        cudaFuncSetAttribute(gru_layer, cudaFuncAttributeMaxDynamicSharedMemorySize, GRU_SMEM);
        cudaFuncSetAttribute(tgemm128, cudaFuncAttributeMaxDynamicSharedMemorySize, TG_SMEM);
        attr_set = 1;
    }

    void* p;
    cudaGetSymbolAddress(&p, g_qkv);   float* qkv  = (float*)p;
    cudaGetSymbolAddress(&p, g_att);   float* att  = (float*)p;
    cudaGetSymbolAddress(&p, g_x);     float* x    = (float*)p;
    cudaGetSymbolAddress(&p, g_xwT);   float* xwT  = (float*)p;
    cudaGetSymbolAddress(&p, g_hseqT); float* hsq  = (float*)p;

    const size_t DIRSTRIDE = (size_t)512 * 32 * G3;

    // 1. QKV projection
    tgemm128<<<dim3(G3 / 128, MTOT / 128), 256, TG_SMEM>>>(emb, ipw, ipb, qkv, MTOT, G3, 768, 0, 0);
    // 2. attention
    attn_scores<<<dim3(8, 8, 256), 256>>>();
    attn_softmax<<<16384, 256>>>();
    attn_av<<<dim3(8, 256), 256>>>();
    // 3. out projection
    tgemm128<<<dim3(768 / 128, MTOT / 128), 256, TG_SMEM>>>(att, opw, opb, x, MTOT, 768, 768, 0, 0);

    // 4. GRU layers
    for (int l = 0; l < 2; l++) {
        const float* xin  = l ? hsq : x;
        int gather        = l ? 1 : 0;
        int K             = l ? 1536 : 768;
        const float* wihF = l ? wih1f : wih0f;
        const float* wihB = l ? wih1b : wih0b;
        const float* bihF = l ? bih1f : bih0f;
        const float* bihB = l ? bih1b : bih0b;
        const float* whhF = l ? whh1f : whh0f;
        const float* whhB = l ? whh1b : whh0b;
        const float* bhhF = l ? bhh1f : bhh0f;
        const float* bhhB = l ? bhh1b : bhh0b;

        tgemm128<<<dim3(G3 / 128, MTOT / 128), 256, TG_SMEM>>>(xin, wihF, bihF, xwT, MTOT, G3, K, gather, 1);
        tgemm128<<<dim3(G3 / 128, MTOT / 128), 256, TG_SMEM>>>(xin, wihB, bihB, xwT + DIRSTRIDE, MTOT, G3, K, gather, 1);
        gru_reset<<<384, 256>>>();
        gru_layer<<<GNB, 256, GRU_SMEM>>>(whhF, whhB, bhhF, bhhB);
    }

    // 5. FC + CRF + Viterbi
    fc_kernel<<<MTOT / 8, 256>>>(fcw, fcb);
    crf_nll_kernel<<<32, 32>>>(lab, cstart, cend, ctr);
    finalize_loss<<<1, 1>>>(out);
    viterbi_kernel<<<32, 32>>>(cstart, cend, ctr, out);
}